// round 14
// baseline (speedup 1.0000x reference)
#include <cuda_runtime.h>
#include <cuda_fp16.h>

#define NN 50000
#define EE 800000
#define SP 136
#define SPH 72   // half2 words per row of fp16 tiles, padded
#define NTILE_E (EE / 128)
#define NTILE_N ((NN + 127) / 128)
#define PGRID 148

// ---------------- scratch (device globals) ----------------------------------
__device__ int      g_is64;
__device__ int      g_src[EE];
__device__ int      g_dst[EE];
__device__ unsigned g_Ah[NN * 64];   // h @ We1[0:128], half2-packed
__device__ unsigned g_Bh[NN * 64];   // h @ We1[128:256], half2-packed
__device__ float    g_agg[NN * 128]; // segment-sum of m (fp32)

__device__ __forceinline__ float siluf(float v) {
    float t;
    asm("tanh.approx.f32 %0, %1;" : "=f"(t) : "f"(0.5f * v));
    return 0.5f * v * (1.0f + t);
}

__device__ __forceinline__ unsigned f2tf(float v) {
    unsigned u;
    asm("cvt.rna.tf32.f32 %0, %1;" : "=r"(u) : "f"(v));
    return u;
}

// permuted slot of k within its 8-group (tf32): pairs (t, t+4) adjacent
__device__ __forceinline__ int kpos(int k) {
    return (k & ~7) + ((k & 3) * 2 + ((k >> 2) & 1));
}

// permuted slot of half2 index j within its 8-half2 group
__device__ __forceinline__ int hslot(int j) {
    return (j & ~7) + ((j & 3) * 2 + ((j >> 2) & 1));
}

__device__ __forceinline__ unsigned pack_h2(float a, float b) {
    __half2 h = __floats2half2_rn(a, b);
    return *(unsigned*)&h;
}

__device__ __forceinline__ float2 unpack_h2(unsigned u) {
    __half2 h = *(__half2*)&u;
    return __half22float2(h);
}

__device__ __forceinline__ void mma8(float* c, const unsigned* a, const unsigned* b) {
    asm volatile(
        "mma.sync.aligned.m16n8k8.row.col.f32.tf32.tf32.f32 "
        "{%0,%1,%2,%3},{%4,%5,%6,%7},{%8,%9},{%0,%1,%2,%3};"
        : "+f"(c[0]), "+f"(c[1]), "+f"(c[2]), "+f"(c[3])
        : "r"(a[0]), "r"(a[1]), "r"(a[2]), "r"(a[3]), "r"(b[0]), "r"(b[1]));
}

__device__ __forceinline__ void mma16h(float* c, const unsigned* a, const unsigned* b) {
    asm volatile(
        "mma.sync.aligned.m16n8k16.row.col.f32.f16.f16.f32 "
        "{%0,%1,%2,%3},{%4,%5,%6,%7},{%8,%9},{%0,%1,%2,%3};"
        : "+f"(c[0]), "+f"(c[1]), "+f"(c[2]), "+f"(c[3])
        : "r"(a[0]), "r"(a[1]), "r"(a[2]), "r"(a[3]), "r"(b[0]), "r"(b[1]));
}

// ---- stage weight 128x128 -> half2 WT[n][hslot(j)] (1024 thr) --------------
__device__ __forceinline__ void stage_wth1024(unsigned* wt, const float* __restrict__ W,
                                              int tid) {
#pragma unroll
    for (int s = 0; s < 8; s++) {
        int i = s * 1024 + tid;
        int n = i & 127, j = i >> 7;
        wt[n * SPH + hslot(j)] = pack_h2(W[(2 * j) * 128 + n], W[(2 * j + 1) * 128 + n]);
    }
}

// ---- fp16 k-loop: M=16, N=32, K=128 ----------------------------------------
__device__ __forceinline__ void gemm_kloop16h(const unsigned* sA, const unsigned* wt,
                                              int mrow, int ncol, int lane,
                                              float acc[4][4]) {
    int g = lane >> 2, tg = lane & 3;
    const unsigned* a0 = sA + (mrow + g) * SPH + 2 * tg;
    const unsigned* b0 = wt + (ncol + g) * SPH + 2 * tg;
#pragma unroll
    for (int kk = 0; kk < 8; kk++) {
        int k0 = kk * 8;
        uint2 r0 = *(const uint2*)(a0 + k0);
        uint2 r1 = *(const uint2*)(a0 + 8 * SPH + k0);
        unsigned a[4] = {r0.x, r1.x, r0.y, r1.y};
#pragma unroll
        for (int nt = 0; nt < 4; nt++) {
            uint2 bv = *(const uint2*)(b0 + nt * 8 * SPH + k0);
            unsigned bb[2] = {bv.x, bv.y};
            mma16h(acc[nt], a, bb);
        }
    }
}

// ---------------- index dtype detection -------------------------------------
__global__ void k_detect(const void* ei) {
    if (blockIdx.x == 0 && threadIdx.x == 0) {
        const int* p = (const int*)ei;
        int acc = 0;
        for (int i = 0; i < 64; i++) acc |= p[2 * i + 1];
        g_is64 = (acc == 0) ? 1 : 0;
    }
}

// ---------------- prep: convert indices + zero agg + copy x ------------------
__global__ void k_prep(const void* ei, const float* __restrict__ x,
                       float* __restrict__ outx) {
    int stride = gridDim.x * blockDim.x;
    int base = blockIdx.x * blockDim.x + threadIdx.x;
    if (g_is64) {
        const long long* p = (const long long*)ei;
        for (int e = base; e < EE; e += stride) {
            g_src[e] = (int)p[e];
            g_dst[e] = (int)p[EE + e];
        }
    } else {
        const int* p = (const int*)ei;
        for (int e = base; e < EE; e += stride) {
            g_src[e] = p[e];
            g_dst[e] = p[EE + e];
        }
    }
    for (int i = base; i < NN * 128; i += stride) {
        g_agg[i] = 0.0f;
        if (i < NN * 3) outx[i] = x[i];
    }
}

// ---------------- node pre-GEMM (persistent, 1024 thr, fp16) ----------------
__global__ __launch_bounds__(1024, 1) void k_node_pre(
    const float* __restrict__ h, const float* __restrict__ We1) {
    extern __shared__ float sm[];
    unsigned* hh = (unsigned*)sm;        // 128*SPH half2 perm
    unsigned* wtA = hh + 128 * SPH;
    unsigned* wtB = wtA + 128 * SPH;

    int tid = threadIdx.x, lane = tid & 31, warp = tid >> 5;
    stage_wth1024(wtA, We1, tid);
    stage_wth1024(wtB, We1 + 128 * 128, tid);
    __syncthreads();

    int mrow = (warp >> 2) * 16, ncol = (warp & 3) * 32;
    int g = lane >> 2, tg = lane & 3;

    for (int t = blockIdx.x; t < NTILE_N; t += gridDim.x) {
        int n0 = t * 128;
#pragma unroll
        for (int v = 0; v < 4; v++) {
            int f = v * 1024 + tid;
            int r = f >> 5, c4 = (f & 31) * 4;
            float4 val = make_float4(0.f, 0.f, 0.f, 0.f);
            if (n0 + r < NN) val = *(const float4*)&h[(n0 + r) * 128 + c4];
            int ci = c4 >> 1;
            hh[r * SPH + hslot(ci)] = pack_h2(val.x, val.y);
            hh[r * SPH + hslot(ci + 1)] = pack_h2(val.z, val.w);
        }
        __syncthreads();
#pragma unroll
        for (int half = 0; half < 2; half++) {
            float acc[4][4];
#pragma unroll
            for (int nt = 0; nt < 4; nt++)
#pragma unroll
                for (int l = 0; l < 4; l++) acc[nt][l] = 0.f;
            gemm_kloop16h(hh, half ? wtB : wtA, mrow, ncol, lane, acc);
            unsigned* out = half ? g_Bh : g_Ah;
#pragma unroll
            for (int nt = 0; nt < 4; nt++) {
                int r = mrow + g;
                int cb = ncol + nt * 8 + tg * 2;
                if (n0 + r < NN)
                    out[(n0 + r) * 64 + (cb >> 1)] = pack_h2(acc[nt][0], acc[nt][1]);
                if (n0 + r + 8 < NN)
                    out[(n0 + r + 8) * 64 + (cb >> 1)] = pack_h2(acc[nt][2], acc[nt][3]);
            }
        }
        __syncthreads();
    }
}

// ---------------- fused edge kernel (persistent, 1024 thr, M=16 fp16) -------
__global__ __launch_bounds__(1024, 1) void k_edge(
    const float* __restrict__ x, const float* __restrict__ ea,
    const float* __restrict__ We1, const float* __restrict__ be1,
    const float* __restrict__ We2, const float* __restrict__ be2,
    const float* __restrict__ Wx1, const float* __restrict__ bx1,
    const float* __restrict__ Wx2, const float* __restrict__ bx2,
    float* __restrict__ outx) {
    extern __shared__ float sm[];
    unsigned* tileh = (unsigned*)sm;        // 128*SPH half2 (s -> mm)
    unsigned* wt2h = tileh + 128 * SPH;     // We2^T fp16 perm
    unsigned* wtxh = wt2h + 128 * SPH;      // Wx1^T fp16 perm
    float* sEA = (float*)(wtxh + 128 * SPH);  // 128*20: ea[16]|dist|si|di|pad
    float* wtE = sEA + 128 * 20;            // 128*16: edge-attr block, tf32 perm
    float* wds = wtE + 128 * 16;
    float* be1s = wds + 128;
    float* be2s = be1s + 128;
    float* bx1s = be2s + 128;
    float* wx2s = bx1s + 128;
    float* sgate = wx2s + 128;              // 2*128 (double-buffered)

    int tid = threadIdx.x, lane = tid & 31, warp = tid >> 5;

    // ---- one-time staging ----
    stage_wth1024(wt2h, We2, tid);
    stage_wth1024(wtxh, Wx1, tid);
#pragma unroll
    for (int s = 0; s < 2; s++) {
        int i = s * 1024 + tid;
        int n = i & 127, k = i >> 7;
        wtE[n * 16 + kpos(k)] = __uint_as_float(f2tf(We1[(256 + k) * 128 + n]));
    }
    if (tid < 128) {
        wds[tid] = We1[272 * 128 + tid];
        be1s[tid] = be1[tid];
        be2s[tid] = be2[tid];
        bx1s[tid] = bx1[tid];
        wx2s[tid] = Wx2[tid];
    }
    float bx2v = bx2[0];

    // warp tile: M=16 (8 m-tiles), N=32 (4 n-tiles)
    int mrow = (warp >> 2) * 16, ncol = (warp & 3) * 32;
    int g = lane >> 2, tg = lane & 3;
    int e_l = tid >> 3, q = tid & 7;  // 8 threads per edge row for staging

    // ---- stage first tile ----
    {
        int e = blockIdx.x * 128 + e_l;
        *(float2*)&sEA[e_l * 20 + q * 2] = *(const float2*)&ea[e * 16 + q * 2];
        if (q == 0) {
            int si = g_src[e], di = g_dst[e];
            float dx = x[di * 3 + 0] - x[si * 3 + 0];
            float dy = x[di * 3 + 1] - x[si * 3 + 1];
            float dz = x[di * 3 + 2] - x[si * 3 + 2];
            sEA[e_l * 20 + 16] = sqrtf(dx * dx + dy * dy + dz * dz + 1e-9f);
            ((int*)sEA)[e_l * 20 + 17] = si;
            ((int*)sEA)[e_l * 20 + 18] = di;
        }
        if (tid < 128) sgate[tid] = bx2v;
    }
    __syncthreads();

    int pb = 0;
    for (int t = blockIdx.x; t < NTILE_E; t += PGRID) {
        float* sg_cur = sgate + pb * 128;
        float* sg_nxt = sgate + (pb ^ 1) * 128;
        int tn = t + PGRID;
        bool hn = tn < NTILE_E;

        // ---- ea-GEMM (K=16, M=16, tf32) + fused fp16 gather + silu -> tileh -
        {
            float acc[4][4];
#pragma unroll
            for (int nt = 0; nt < 4; nt++)
#pragma unroll
                for (int l = 0; l < 4; l++) acc[nt][l] = 0.f;
            const float* a0p = sEA + (mrow + g) * 20 + tg;
            const float* b0p = wtE + (ncol + g) * 16 + 2 * tg;
#pragma unroll
            for (int kk = 0; kk < 2; kk++) {
                int k0 = kk * 8;
                unsigned a[4];
                a[0] = f2tf(a0p[k0]);
                a[1] = f2tf(a0p[8 * 20 + k0]);
                a[2] = f2tf(a0p[k0 + 4]);
                a[3] = f2tf(a0p[8 * 20 + k0 + 4]);
#pragma unroll
                for (int nt = 0; nt < 4; nt++) {
                    float2 b = *(const float2*)(b0p + nt * 8 * 16 + k0);
                    unsigned bb[2] = {__float_as_uint(b.x), __float_as_uint(b.y)};
                    mma8(acc[nt], a, bb);
                }
            }
#pragma unroll
            for (int rr = 0; rr < 2; rr++) {
                int row = mrow + g + rr * 8;
                int si = ((const int*)sEA)[row * 20 + 17];
                int di = ((const int*)sEA)[row * 20 + 18];
                float dist = sEA[row * 20 + 16];
#pragma unroll
                for (int nt = 0; nt < 4; nt++) {
                    int c = ncol + nt * 8 + tg * 2;
                    float2 a2 = unpack_h2(g_Ah[si * 64 + (c >> 1)]);
                    float2 b2 = unpack_h2(g_Bh[di * 64 + (c >> 1)]);
                    float v0 = acc[nt][rr * 2 + 0] + dist * wds[c] + be1s[c] + a2.x + b2.x;
                    float v1 = acc[nt][rr * 2 + 1] + dist * wds[c + 1] + be1s[c + 1] +
                               a2.y + b2.y;
                    tileh[row * SPH + hslot(c >> 1)] = pack_h2(siluf(v0), siluf(v1));
                }
            }
        }
        __syncthreads();  // A

        // ---- GEMM1 (fp16): mm = s @ We2 + be2 ----
        float accm[4][4];
#pragma unroll
        for (int nt = 0; nt < 4; nt++) {
            int cb = ncol + nt * 8 + tg * 2;
            float b0v = be2s[cb], b1v = be2s[cb + 1];
            accm[nt][0] = b0v; accm[nt][1] = b1v;
            accm[nt][2] = b0v; accm[nt][3] = b1v;
        }
        gemm_kloop16h(tileh, wt2h, mrow, ncol, lane, accm);

        // agg scatter: pair-merge via shfl -> red.v4
#pragma unroll
        for (int rr = 0; rr < 2; rr++) {
            int row = mrow + g + rr * 8;
            int di = ((const int*)sEA)[row * 20 + 18];
#pragma unroll
            for (int nt = 0; nt < 4; nt++) {
                float v0 = accm[nt][rr * 2 + 0];
                float v1 = accm[nt][rr * 2 + 1];
                float o0 = __shfl_xor_sync(0xffffffffu, v0, 1);
                float o1 = __shfl_xor_sync(0xffffffffu, v1, 1);
                if ((tg & 1) == 0) {
                    int c = ncol + nt * 8 + tg * 2;
                    asm volatile("red.global.add.v4.f32 [%0], {%1,%2,%3,%4};"
                                 :: "l"(&g_agg[di * 128 + c]),
                                    "f"(v0), "f"(v1), "f"(o0), "f"(o1)
                                 : "memory");
                }
            }
        }
        __syncthreads();  // B

        // store mm into tileh (fp16 perm)
#pragma unroll
        for (int rr = 0; rr < 2; rr++) {
            int row = mrow + g + rr * 8;
#pragma unroll
            for (int nt = 0; nt < 4; nt++) {
                int c = ncol + nt * 8 + tg * 2;
                tileh[row * SPH + hslot(c >> 1)] =
                    pack_h2(accm[nt][rr * 2 + 0], accm[nt][rr * 2 + 1]);
            }
        }
        __syncthreads();  // C

        // ---- prefetch next tile (regs) + snapshot scatter info ----
        float2 pea;
        int psi = 0, pdi = 0;
        float pdx = 0.f, pdy = 0.f, pdz = 0.f;
        if (hn) {
            int e = tn * 128 + e_l;
            pea = *(const float2*)&ea[e * 16 + q * 2];
            if (q == 0) {
                psi = g_src[e];
                pdi = g_dst[e];
                pdx = x[pdi * 3 + 0] - x[psi * 3 + 0];
                pdy = x[pdi * 3 + 1] - x[psi * 3 + 1];
                pdz = x[pdi * 3 + 2] - x[psi * 3 + 2];
            }
        }
        int xsi = 0, xdi = 0;
        if (tid < 128) {
            xsi = ((const int*)sEA)[tid * 20 + 17];
            xdi = ((const int*)sEA)[tid * 20 + 18];
        }

        // ---- GEMM2 (fp16): gate = sum silu(mm@Wx1+bx1)*wx2 ----
        {
            float acc[4][4];
#pragma unroll
            for (int nt = 0; nt < 4; nt++) {
                int cb = ncol + nt * 8 + tg * 2;
                float b0v = bx1s[cb], b1v = bx1s[cb + 1];
                acc[nt][0] = b0v; acc[nt][1] = b1v;
                acc[nt][2] = b0v; acc[nt][3] = b1v;
            }
            gemm_kloop16h(tileh, wtxh, mrow, ncol, lane, acc);
            float p0 = 0.f, p1 = 0.f;
#pragma unroll
            for (int nt = 0; nt < 4; nt++) {
                int cb = ncol + nt * 8 + tg * 2;
                float w0 = wx2s[cb], w1 = wx2s[cb + 1];
                p0 += siluf(acc[nt][0]) * w0 + siluf(acc[nt][1]) * w1;
                p1 += siluf(acc[nt][2]) * w0 + siluf(acc[nt][3]) * w1;
            }
            p0 += __shfl_xor_sync(0xffffffffu, p0, 1);
            p0 += __shfl_xor_sync(0xffffffffu, p0, 2);
            p1 += __shfl_xor_sync(0xffffffffu, p1, 1);
            p1 += __shfl_xor_sync(0xffffffffu, p1, 2);
            if (tg == 0) {
                atomicAdd(&sg_cur[mrow + g], p0);
                atomicAdd(&sg_cur[mrow + g + 8], p1);
            }
        }
        __syncthreads();  // D

        // ---- x scatter + stage next tile ----
        if (tid < 128) {
            float dx = x[xdi * 3 + 0] - x[xsi * 3 + 0];
            float dy = x[xdi * 3 + 1] - x[xsi * 3 + 1];
            float dz = x[xdi * 3 + 2] - x[xsi * 3 + 2];
            float rn = __fdividef(1.0f, sqrtf(dx * dx + dy * dy + dz * dz) + 1e-9f);
            float gte = sg_cur[tid];
            atomicAdd(&outx[xdi * 3 + 0], dx * rn * gte);
            atomicAdd(&outx[xdi * 3 + 1], dy * rn * gte);
            atomicAdd(&outx[xdi * 3 + 2], dz * rn * gte);
            sg_nxt[tid] = bx2v;
        }
        if (hn) {
            *(float2*)&sEA[e_l * 20 + q * 2] = pea;
            if (q == 0) {
                sEA[e_l * 20 + 16] = sqrtf(pdx * pdx + pdy * pdy + pdz * pdz + 1e-9f);
                ((int*)sEA)[e_l * 20 + 17] = psi;
                ((int*)sEA)[e_l * 20 + 18] = pdi;
            }
        }
        __syncthreads();  // E
        pb ^= 1;
    }
}

// ---------------- node update (persistent, 1024 thr, fp16 GEMMs) ------------
__global__ __launch_bounds__(1024, 1) void k_node_upd(
    const float* __restrict__ h, const float* __restrict__ Wh1,
    const float* __restrict__ bh1, const float* __restrict__ Wh2,
    const float* __restrict__ bh2, const float* __restrict__ lng,
    const float* __restrict__ lnb, float* __restrict__ outh) {
    extern __shared__ float sm[];
    float* hr = sm;                        // 128*SP fp32 (residual + LN)
    unsigned* hh = (unsigned*)(hr + 128 * SP);  // 128*SPH h half2 perm
    unsigned* ap = hh + 128 * SPH;         // 128*SPH agg -> tt half2 perm
    unsigned* wt = ap + 128 * SPH;         // 128*SPH weight half2 perm
    float* bh1s = (float*)(wt + 128 * SPH);
    float* bh2s = bh1s + 128;
    float* lngs = bh2s + 128;
    float* lnbs = lngs + 128;
    float* ssum = lnbs + 128;
    float* ssq = ssum + 128;

    int tid = threadIdx.x, lane = tid & 31, warp = tid >> 5;
    if (tid < 128) {
        bh1s[tid] = bh1[tid];
        bh2s[tid] = bh2[tid];
        lngs[tid] = lng[tid];
        lnbs[tid] = lnb[tid];
    }

    int mrow = (warp >> 2) * 16, ncol = (warp & 3) * 32;
    int g = lane >> 2, tg = lane & 3;

    for (int t = blockIdx.x; t < NTILE_N; t += gridDim.x) {
        int n0 = t * 128;
        if (tid < 128) {
            ssum[tid] = 0.f;
            ssq[tid] = 0.f;
        }
#pragma unroll
        for (int v = 0; v < 4; v++) {
            int f = v * 1024 + tid;
            int r = f >> 5, c4 = (f & 31) * 4;
            float4 hv = make_float4(0.f, 0.f, 0.f, 0.f);
            float4 av = make_float4(0.f, 0.f, 0.f, 0.f);
            if (n0 + r < NN) {
                hv = *(const float4*)&h[(n0 + r) * 128 + c4];
                av = *(const float4*)&g_agg[(n0 + r) * 128 + c4];
            }
            *(float4*)&hr[r * SP + c4] = hv;
            int ci = c4 >> 1;
            hh[r * SPH + hslot(ci)] = pack_h2(hv.x, hv.y);
            hh[r * SPH + hslot(ci + 1)] = pack_h2(hv.z, hv.w);
            ap[r * SPH + hslot(ci)] = pack_h2(av.x, av.y);
            ap[r * SPH + hslot(ci + 1)] = pack_h2(av.z, av.w);
        }
        stage_wth1024(wt, Wh1, tid);
        __syncthreads();

        float acc[4][4];
#pragma unroll
        for (int nt = 0; nt < 4; nt++) {
            int cb = ncol + nt * 8 + tg * 2;
            float b0v = bh1s[cb], b1v = bh1s[cb + 1];
            acc[nt][0] = b0v; acc[nt][1] = b1v;
            acc[nt][2] = b0v; acc[nt][3] = b1v;
        }
        gemm_kloop16h(hh, wt, mrow, ncol, lane, acc);
        __syncthreads();
        stage_wth1024(wt, Wh1 + 128 * 128, tid);
        __syncthreads();
        gemm_kloop16h(ap, wt, mrow, ncol, lane, acc);
        __syncthreads();

#pragma unroll
        for (int rr = 0; rr < 2; rr++) {
            int row = mrow + g + rr * 8;
#pragma unroll
            for (int nt = 0; nt < 4; nt++) {
                int c = ncol + nt * 8 + tg * 2;
                ap[row * SPH + hslot(c >> 1)] =
                    pack_h2(siluf(acc[nt][rr * 2 + 0]), siluf(acc[nt][rr * 2 + 1]));
            }
        }
        stage_wth1024(wt, Wh2, tid);
        __syncthreads();

        float acc2[4][4];
#pragma unroll
        for (int nt = 0; nt < 4; nt++) {
            int cb = ncol + nt * 8 + tg * 2;
            float b0v = bh2s[cb], b1v = bh2s[cb + 1];
            acc2[nt][0] = b0v; acc2[nt][1] = b1v;
            acc2[nt][2] = b0v; acc2[nt][3] = b1v;
        }
        gemm_kloop16h(ap, wt, mrow, ncol, lane, acc2);

        float vsum[2] = {0.f, 0.f}, vsq[2] = {0.f, 0.f};
#pragma unroll
        for (int rr = 0; rr < 2; rr++) {
            int row = mrow + g + rr * 8;
#pragma unroll
            for (int nt = 0; nt < 4; nt++) {
                int cb = ncol + nt * 8 + tg * 2;
                float v0 = hr[row * SP + cb] + acc2[nt][rr * 2 + 0];
                float v1 = hr[row * SP + cb + 1] + acc2[nt][rr * 2 + 1];
                acc2[nt][rr * 2 + 0] = v0;
                acc2[nt][rr * 2 + 1] = v1;
                vsum[rr] += v0 + v1;
                vsq[rr] += v0 * v0 + v1 * v1;
            }
        }
#pragma unroll
        for (int i = 0; i < 2; i++) {
            vsum[i] += __shfl_xor_sync(0xffffffffu, vsum[i], 1);
            vsum[i] += __shfl_xor_sync(0xffffffffu, vsum[i], 2);
            vsq[i] += __shfl_xor_sync(0xffffffffu, vsq[i], 1);
            vsq[i] += __shfl_xor_sync(0xffffffffu, vsq[i], 2);
        }
        if (tg == 0) {
            atomicAdd(&ssum[mrow + g], vsum[0]);
            atomicAdd(&ssq[mrow + g], vsq[0]);
            atomicAdd(&ssum[mrow + g + 8], vsum[1]);
            atomicAdd(&ssq[mrow + g + 8], vsq[1]);
        }
        __syncthreads();

#pragma unroll
        for (int rr = 0; rr < 2; rr++) {
            int row = mrow + g + rr * 8;
            float mean = ssum[row] * (1.0f / 128.0f);
            float var = ssq[row] * (1.0f / 128.0f) - mean * mean;
            float rstd = rsqrtf(var + 1e-5f);
            if (n0 + row < NN) {
#pragma unroll
                for (int nt = 0; nt < 4; nt++) {
                    int cb = ncol + nt * 8 + tg * 2;
                    *(float2*)&outh[(n0 + row) * 128 + cb] = make_float2(
                        (acc2[nt][rr * 2 + 0] - mean) * rstd * lngs[cb] + lnbs[cb],
                        (acc2[nt][rr * 2 + 1] - mean) * rstd * lngs[cb + 1] + lnbs[cb + 1]);
                }
            }
        }
        __syncthreads();
    }
}

// ---------------- launcher ---------------------------------------------------
extern "C" void kernel_launch(void* const* d_in, const int* in_sizes, int n_in,
                              void* d_out, int out_size) {
    const float* h = (const float*)d_in[0];
    const float* x = (const float*)d_in[1];
    const void* ei = d_in[2];
    const float* ea = (const float*)d_in[3];
    const float* We1 = (const float*)d_in[4];
    const float* be1 = (const float*)d_in[5];
    const float* We2 = (const float*)d_in[6];
    const float* be2 = (const float*)d_in[7];
    const float* Wh1 = (const float*)d_in[8];
    const float* bh1 = (const float*)d_in[9];
    const float* Wh2 = (const float*)d_in[10];
    const float* bh2 = (const float*)d_in[11];
    const float* Wx1 = (const float*)d_in[12];
    const float* bx1 = (const float*)d_in[13];
    const float* Wx2 = (const float*)d_in[14];
    const float* bx2 = (const float*)d_in[15];
    const float* lng = (const float*)d_in[16];
    const float* lnb = (const float*)d_in[17];

    float* outh = (float*)d_out;
    float* outx = outh + (size_t)NN * 128;

    const int SMEM_EDGE = (3 * 128 * SPH + 128 * 20 + 128 * 16 + 5 * 128 + 256) * 4;  // 132608
    const int SMEM_PRE = (3 * 128 * SPH) * 4;                                          // 110592
    const int SMEM_UPD = (128 * SP + 3 * 128 * SPH + 6 * 128) * 4;                     // 183296
    cudaFuncSetAttribute(k_edge, cudaFuncAttributeMaxDynamicSharedMemorySize, SMEM_EDGE);
    cudaFuncSetAttribute(k_node_pre, cudaFuncAttributeMaxDynamicSharedMemorySize, SMEM_PRE);
    cudaFuncSetAttribute(k_node_upd, cudaFuncAttributeMaxDynamicSharedMemorySize, SMEM_UPD);

    k_detect<<<1, 32>>>(ei);
    k_prep<<<1024, 256>>>(ei, x, outx);
    k_node_pre<<<PGRID, 1024, SMEM_PRE>>>(h, We1);
    k_edge<<<PGRID, 1024, SMEM_EDGE>>>(x, ea, We1, be1, We2, be2, Wx1, bx1, Wx2,
                                       bx2, outx);
    k_node_upd<<<PGRID, 1024, SMEM_UPD>>>(h, Wh1, bh1, Wh2, bh2, lng, lnb, outh);
}

// round 15
// speedup vs baseline: 1.0816x; 1.0816x over previous
#include <cuda_runtime.h>
#include <cuda_fp16.h>

#define NN 50000
#define EE 800000
#define SP 136
#define SPH 72   // half2 words per row of fp16 tiles, padded
#define EAW 24   // sEA row: ea[16]|dist|si|di|pad|ux|uy|uz|pad
#define NTILE_E (EE / 128)
#define NTILE_N ((NN + 127) / 128)
#define PGRID 148

// ---------------- scratch (device globals) ----------------------------------
__device__ int      g_is64;
__device__ int      g_src[EE];
__device__ int      g_dst[EE];
__device__ unsigned g_Ah[NN * 64];   // h @ We1[0:128], half2-packed
__device__ unsigned g_Bh[NN * 64];   // h @ We1[128:256], half2-packed
__device__ float    g_agg[NN * 128]; // segment-sum of m (fp32)

__device__ __forceinline__ float siluf(float v) {
    float t;
    asm("tanh.approx.f32 %0, %1;" : "=f"(t) : "f"(0.5f * v));
    return 0.5f * v * (1.0f + t);
}

__device__ __forceinline__ unsigned f2tf(float v) {
    unsigned u;
    asm("cvt.rna.tf32.f32 %0, %1;" : "=r"(u) : "f"(v));
    return u;
}

// permuted slot of k within its 8-group (tf32): pairs (t, t+4) adjacent
__device__ __forceinline__ int kpos(int k) {
    return (k & ~7) + ((k & 3) * 2 + ((k >> 2) & 1));
}

// permuted slot of half2 index j within its 8-half2 group
__device__ __forceinline__ int hslot(int j) {
    return (j & ~7) + ((j & 3) * 2 + ((j >> 2) & 1));
}

__device__ __forceinline__ unsigned pack_h2(float a, float b) {
    __half2 h = __floats2half2_rn(a, b);
    return *(unsigned*)&h;
}

__device__ __forceinline__ float2 unpack_h2(unsigned u) {
    __half2 h = *(__half2*)&u;
    return __half22float2(h);
}

__device__ __forceinline__ void mma8(float* c, const unsigned* a, const unsigned* b) {
    asm volatile(
        "mma.sync.aligned.m16n8k8.row.col.f32.tf32.tf32.f32 "
        "{%0,%1,%2,%3},{%4,%5,%6,%7},{%8,%9},{%0,%1,%2,%3};"
        : "+f"(c[0]), "+f"(c[1]), "+f"(c[2]), "+f"(c[3])
        : "r"(a[0]), "r"(a[1]), "r"(a[2]), "r"(a[3]), "r"(b[0]), "r"(b[1]));
}

__device__ __forceinline__ void mma16h(float* c, const unsigned* a, const unsigned* b) {
    asm volatile(
        "mma.sync.aligned.m16n8k16.row.col.f32.f16.f16.f32 "
        "{%0,%1,%2,%3},{%4,%5,%6,%7},{%8,%9},{%0,%1,%2,%3};"
        : "+f"(c[0]), "+f"(c[1]), "+f"(c[2]), "+f"(c[3])
        : "r"(a[0]), "r"(a[1]), "r"(a[2]), "r"(a[3]), "r"(b[0]), "r"(b[1]));
}

// ---- stage weight 128x128 -> half2 WT[n][hslot(j)] --------------------------
__device__ __forceinline__ void stage_wth512(unsigned* wt, const float* __restrict__ W,
                                             int tid) {
#pragma unroll
    for (int s = 0; s < 16; s++) {
        int i = s * 512 + tid;
        int n = i & 127, j = i >> 7;
        wt[n * SPH + hslot(j)] = pack_h2(W[(2 * j) * 128 + n], W[(2 * j + 1) * 128 + n]);
    }
}

__device__ __forceinline__ void stage_wth1024(unsigned* wt, const float* __restrict__ W,
                                              int tid) {
#pragma unroll
    for (int s = 0; s < 8; s++) {
        int i = s * 1024 + tid;
        int n = i & 127, j = i >> 7;
        wt[n * SPH + hslot(j)] = pack_h2(W[(2 * j) * 128 + n], W[(2 * j + 1) * 128 + n]);
    }
}

// ---- fp16 k-loop: M=16, N=32, K=128 (node kernels, 32 warps) ---------------
__device__ __forceinline__ void gemm_kloop16h(const unsigned* sA, const unsigned* wt,
                                              int mrow, int ncol, int lane,
                                              float acc[4][4]) {
    int g = lane >> 2, tg = lane & 3;
    const unsigned* a0 = sA + (mrow + g) * SPH + 2 * tg;
    const unsigned* b0 = wt + (ncol + g) * SPH + 2 * tg;
#pragma unroll
    for (int kk = 0; kk < 8; kk++) {
        int k0 = kk * 8;
        uint2 r0 = *(const uint2*)(a0 + k0);
        uint2 r1 = *(const uint2*)(a0 + 8 * SPH + k0);
        unsigned a[4] = {r0.x, r1.x, r0.y, r1.y};
#pragma unroll
        for (int nt = 0; nt < 4; nt++) {
            uint2 bv = *(const uint2*)(b0 + nt * 8 * SPH + k0);
            unsigned bb[2] = {bv.x, bv.y};
            mma16h(acc[nt], a, bb);
        }
    }
}

// ---- fp16 k-loop: M=32, N=32, K=128 (edge kernel, 16 warps) ----------------
__device__ __forceinline__ void gemm_kloop32h(const unsigned* sA, const unsigned* wt,
                                              int mrow, int ncol, int lane,
                                              float accA[4][4], float accB[4][4]) {
    int g = lane >> 2, tg = lane & 3;
    const unsigned* a0 = sA + (mrow + g) * SPH + 2 * tg;
    const unsigned* b0 = wt + (ncol + g) * SPH + 2 * tg;
#pragma unroll
    for (int kk = 0; kk < 8; kk++) {
        int k0 = kk * 8;
        uint2 r0 = *(const uint2*)(a0 + k0);
        uint2 r1 = *(const uint2*)(a0 + 8 * SPH + k0);
        uint2 r2 = *(const uint2*)(a0 + 16 * SPH + k0);
        uint2 r3 = *(const uint2*)(a0 + 24 * SPH + k0);
        unsigned aA[4] = {r0.x, r1.x, r0.y, r1.y};
        unsigned aB[4] = {r2.x, r3.x, r2.y, r3.y};
#pragma unroll
        for (int nt = 0; nt < 4; nt++) {
            uint2 bv = *(const uint2*)(b0 + nt * 8 * SPH + k0);
            unsigned bb[2] = {bv.x, bv.y};
            mma16h(accA[nt], aA, bb);
            mma16h(accB[nt], aB, bb);
        }
    }
}

// ---------------- index dtype detection -------------------------------------
__global__ void k_detect(const void* ei) {
    if (blockIdx.x == 0 && threadIdx.x == 0) {
        const int* p = (const int*)ei;
        int acc = 0;
        for (int i = 0; i < 64; i++) acc |= p[2 * i + 1];
        g_is64 = (acc == 0) ? 1 : 0;
    }
}

// ---------------- prep: convert indices + zero agg + copy x ------------------
__global__ void k_prep(const void* ei, const float* __restrict__ x,
                       float* __restrict__ outx) {
    int stride = gridDim.x * blockDim.x;
    int base = blockIdx.x * blockDim.x + threadIdx.x;
    if (g_is64) {
        const long long* p = (const long long*)ei;
        for (int e = base; e < EE; e += stride) {
            g_src[e] = (int)p[e];
            g_dst[e] = (int)p[EE + e];
        }
    } else {
        const int* p = (const int*)ei;
        for (int e = base; e < EE; e += stride) {
            g_src[e] = p[e];
            g_dst[e] = p[EE + e];
        }
    }
    for (int i = base; i < NN * 128; i += stride) {
        g_agg[i] = 0.0f;
        if (i < NN * 3) outx[i] = x[i];
    }
}

// ---------------- node pre-GEMM (persistent, 1024 thr, fp16) ----------------
__global__ __launch_bounds__(1024, 1) void k_node_pre(
    const float* __restrict__ h, const float* __restrict__ We1) {
    extern __shared__ float sm[];
    unsigned* hh = (unsigned*)sm;        // 128*SPH half2 perm
    unsigned* wtA = hh + 128 * SPH;
    unsigned* wtB = wtA + 128 * SPH;

    int tid = threadIdx.x, lane = tid & 31, warp = tid >> 5;
    stage_wth1024(wtA, We1, tid);
    stage_wth1024(wtB, We1 + 128 * 128, tid);
    __syncthreads();

    int mrow = (warp >> 2) * 16, ncol = (warp & 3) * 32;
    int g = lane >> 2, tg = lane & 3;

    for (int t = blockIdx.x; t < NTILE_N; t += gridDim.x) {
        int n0 = t * 128;
#pragma unroll
        for (int v = 0; v < 4; v++) {
            int f = v * 1024 + tid;
            int r = f >> 5, c4 = (f & 31) * 4;
            float4 val = make_float4(0.f, 0.f, 0.f, 0.f);
            if (n0 + r < NN) val = *(const float4*)&h[(n0 + r) * 128 + c4];
            int ci = c4 >> 1;
            hh[r * SPH + hslot(ci)] = pack_h2(val.x, val.y);
            hh[r * SPH + hslot(ci + 1)] = pack_h2(val.z, val.w);
        }
        __syncthreads();
#pragma unroll
        for (int half = 0; half < 2; half++) {
            float acc[4][4];
#pragma unroll
            for (int nt = 0; nt < 4; nt++)
#pragma unroll
                for (int l = 0; l < 4; l++) acc[nt][l] = 0.f;
            gemm_kloop16h(hh, half ? wtB : wtA, mrow, ncol, lane, acc);
            unsigned* out = half ? g_Bh : g_Ah;
#pragma unroll
            for (int nt = 0; nt < 4; nt++) {
                int r = mrow + g;
                int cb = ncol + nt * 8 + tg * 2;
                if (n0 + r < NN)
                    out[(n0 + r) * 64 + (cb >> 1)] = pack_h2(acc[nt][0], acc[nt][1]);
                if (n0 + r + 8 < NN)
                    out[(n0 + r + 8) * 64 + (cb >> 1)] = pack_h2(acc[nt][2], acc[nt][3]);
            }
        }
        __syncthreads();
    }
}

// ---------------- fused edge kernel (persistent, 512 thr, fp16, M=32) -------
__global__ __launch_bounds__(512, 1) void k_edge(
    const float* __restrict__ x, const float* __restrict__ ea,
    const float* __restrict__ We1, const float* __restrict__ be1,
    const float* __restrict__ We2, const float* __restrict__ be2,
    const float* __restrict__ Wx1, const float* __restrict__ bx1,
    const float* __restrict__ Wx2, const float* __restrict__ bx2,
    float* __restrict__ outx) {
    extern __shared__ float sm[];
    unsigned* tileh = (unsigned*)sm;        // 128*SPH half2 (s -> mm)
    unsigned* wt2h = tileh + 128 * SPH;     // We2^T fp16 perm
    unsigned* wtxh = wt2h + 128 * SPH;      // Wx1^T fp16 perm
    float* sEA = (float*)(wtxh + 128 * SPH);  // 128*EAW
    float* wtE = sEA + 128 * EAW;           // 128*16: edge-attr block, tf32 perm
    float* wds = wtE + 128 * 16;
    float* be1s = wds + 128;
    float* be2s = be1s + 128;
    float* bx1s = be2s + 128;
    float* wx2s = bx1s + 128;
    float* sgate = wx2s + 128;              // 2*128 (double-buffered)

    int tid = threadIdx.x, lane = tid & 31, warp = tid >> 5;

    // ---- one-time staging ----
    stage_wth512(wt2h, We2, tid);
    stage_wth512(wtxh, Wx1, tid);
#pragma unroll
    for (int s = 0; s < 4; s++) {
        int i = s * 512 + tid;
        int n = i & 127, k = i >> 7;
        wtE[n * 16 + kpos(k)] = __uint_as_float(f2tf(We1[(256 + k) * 128 + n]));
    }
    if (tid < 128) {
        wds[tid] = We1[272 * 128 + tid];
        be1s[tid] = be1[tid];
        be2s[tid] = be2[tid];
        bx1s[tid] = bx1[tid];
        wx2s[tid] = Wx2[tid];
    }
    float bx2v = bx2[0];

    // warp tile: M=32, N=32
    int mrow = (warp & 3) * 32, ncol = (warp >> 2) * 32;
    int g = lane >> 2, tg = lane & 3;
    int e_l = tid >> 2, q = tid & 3;

    // ---- stage first tile ----
    {
        int e = blockIdx.x * 128 + e_l;
        *(float4*)&sEA[e_l * EAW + q * 4] = *(const float4*)&ea[e * 16 + q * 4];
        if (q == 0) {
            int si = g_src[e], di = g_dst[e];
            float dx = x[di * 3 + 0] - x[si * 3 + 0];
            float dy = x[di * 3 + 1] - x[si * 3 + 1];
            float dz = x[di * 3 + 2] - x[si * 3 + 2];
            float ss2 = dx * dx + dy * dy + dz * dz;
            float rn = __fdividef(1.0f, sqrtf(ss2) + 1e-9f);
            sEA[e_l * EAW + 16] = sqrtf(ss2 + 1e-9f);
            ((int*)sEA)[e_l * EAW + 17] = si;
            ((int*)sEA)[e_l * EAW + 18] = di;
            sEA[e_l * EAW + 20] = dx * rn;
            sEA[e_l * EAW + 21] = dy * rn;
            sEA[e_l * EAW + 22] = dz * rn;
        }
        if (tid < 128) sgate[tid] = bx2v;
    }
    __syncthreads();

    int pb = 0;
    for (int t = blockIdx.x; t < NTILE_E; t += PGRID) {
        float* sg_cur = sgate + pb * 128;
        float* sg_nxt = sgate + (pb ^ 1) * 128;
        int tn = t + PGRID;
        bool hn = tn < NTILE_E;

        // ---- ea-GEMM (K=16, M=32, tf32) + fused fp16 gather + silu -> tileh -
        {
            float accA[4][4], accB[4][4];
#pragma unroll
            for (int nt = 0; nt < 4; nt++)
#pragma unroll
                for (int l = 0; l < 4; l++) { accA[nt][l] = 0.f; accB[nt][l] = 0.f; }
            const float* a0p = sEA + (mrow + g) * EAW + tg;
            const float* b0p = wtE + (ncol + g) * 16 + 2 * tg;
#pragma unroll
            for (int kk = 0; kk < 2; kk++) {
                int k0 = kk * 8;
                unsigned aA[4], aB[4];
                aA[0] = f2tf(a0p[k0]);
                aA[1] = f2tf(a0p[8 * EAW + k0]);
                aA[2] = f2tf(a0p[k0 + 4]);
                aA[3] = f2tf(a0p[8 * EAW + k0 + 4]);
                aB[0] = f2tf(a0p[16 * EAW + k0]);
                aB[1] = f2tf(a0p[24 * EAW + k0]);
                aB[2] = f2tf(a0p[16 * EAW + k0 + 4]);
                aB[3] = f2tf(a0p[24 * EAW + k0 + 4]);
#pragma unroll
                for (int nt = 0; nt < 4; nt++) {
                    float2 b = *(const float2*)(b0p + nt * 8 * 16 + k0);
                    unsigned bb[2] = {__float_as_uint(b.x), __float_as_uint(b.y)};
                    mma8(accA[nt], aA, bb);
                    mma8(accB[nt], aB, bb);
                }
            }
#pragma unroll
            for (int rr = 0; rr < 4; rr++) {
                int row = mrow + g + rr * 8;
                float* ac = (rr < 2) ? &accA[0][0] : &accB[0][0];
                int jo = (rr & 1) * 2;
                int si = ((const int*)sEA)[row * EAW + 17];
                int di = ((const int*)sEA)[row * EAW + 18];
                float dist = sEA[row * EAW + 16];
#pragma unroll
                for (int nt = 0; nt < 4; nt++) {
                    int c = ncol + nt * 8 + tg * 2;
                    float2 a2 = unpack_h2(g_Ah[si * 64 + (c >> 1)]);
                    float2 b2 = unpack_h2(g_Bh[di * 64 + (c >> 1)]);
                    float v0 = ac[nt * 4 + jo + 0] + dist * wds[c] + be1s[c] + a2.x + b2.x;
                    float v1 = ac[nt * 4 + jo + 1] + dist * wds[c + 1] + be1s[c + 1] +
                               a2.y + b2.y;
                    tileh[row * SPH + hslot(c >> 1)] = pack_h2(siluf(v0), siluf(v1));
                }
            }
        }
        __syncthreads();  // A

        // ---- GEMM1 (fp16): mm = s @ We2 + be2 ----
        float accmA[4][4], accmB[4][4];
#pragma unroll
        for (int nt = 0; nt < 4; nt++) {
            int cb = ncol + nt * 8 + tg * 2;
            float b0v = be2s[cb], b1v = be2s[cb + 1];
            accmA[nt][0] = b0v; accmA[nt][1] = b1v;
            accmA[nt][2] = b0v; accmA[nt][3] = b1v;
            accmB[nt][0] = b0v; accmB[nt][1] = b1v;
            accmB[nt][2] = b0v; accmB[nt][3] = b1v;
        }
        gemm_kloop32h(tileh, wt2h, mrow, ncol, lane, accmA, accmB);

        // agg scatter: pair-merge via shfl -> red.v4
#pragma unroll
        for (int rr = 0; rr < 4; rr++) {
            int row = mrow + g + rr * 8;
            const float* ac = (rr < 2) ? &accmA[0][0] : &accmB[0][0];
            int jo = (rr & 1) * 2;
            int di = ((const int*)sEA)[row * EAW + 18];
#pragma unroll
            for (int nt = 0; nt < 4; nt++) {
                float v0 = ac[nt * 4 + jo + 0];
                float v1 = ac[nt * 4 + jo + 1];
                float o0 = __shfl_xor_sync(0xffffffffu, v0, 1);
                float o1 = __shfl_xor_sync(0xffffffffu, v1, 1);
                if ((tg & 1) == 0) {
                    int c = ncol + nt * 8 + tg * 2;
                    asm volatile("red.global.add.v4.f32 [%0], {%1,%2,%3,%4};"
                                 :: "l"(&g_agg[di * 128 + c]),
                                    "f"(v0), "f"(v1), "f"(o0), "f"(o1)
                                 : "memory");
                }
            }
        }
        __syncthreads();  // B

        // store mm into tileh (fp16 perm)
#pragma unroll
        for (int rr = 0; rr < 4; rr++) {
            int row = mrow + g + rr * 8;
            const float* ac = (rr < 2) ? &accmA[0][0] : &accmB[0][0];
            int jo = (rr & 1) * 2;
#pragma unroll
            for (int nt = 0; nt < 4; nt++) {
                int c = ncol + nt * 8 + tg * 2;
                tileh[row * SPH + hslot(c >> 1)] =
                    pack_h2(ac[nt * 4 + jo + 0], ac[nt * 4 + jo + 1]);
            }
        }
        __syncthreads();  // C

        // ---- prefetch next tile (regs) + snapshot scatter info ----
        float4 pea;
        int psi = 0, pdi = 0;
        float pdx = 0.f, pdy = 0.f, pdz = 0.f;
        if (hn) {
            int e = tn * 128 + e_l;
            pea = *(const float4*)&ea[e * 16 + q * 4];
            if (q == 0) {
                psi = g_src[e];
                pdi = g_dst[e];
                pdx = x[pdi * 3 + 0] - x[psi * 3 + 0];
                pdy = x[pdi * 3 + 1] - x[psi * 3 + 1];
                pdz = x[pdi * 3 + 2] - x[psi * 3 + 2];
            }
        }
        int xdi = 0;
        float xux = 0.f, xuy = 0.f, xuz = 0.f;
        if (tid < 128) {
            xdi = ((const int*)sEA)[tid * EAW + 18];
            xux = sEA[tid * EAW + 20];
            xuy = sEA[tid * EAW + 21];
            xuz = sEA[tid * EAW + 22];
        }

        // ---- GEMM2 (fp16): gate = sum silu(mm@Wx1+bx1)*wx2 ----
        {
            float accA[4][4], accB[4][4];
#pragma unroll
            for (int nt = 0; nt < 4; nt++) {
                int cb = ncol + nt * 8 + tg * 2;
                float b0v = bx1s[cb], b1v = bx1s[cb + 1];
                accA[nt][0] = b0v; accA[nt][1] = b1v;
                accA[nt][2] = b0v; accA[nt][3] = b1v;
                accB[nt][0] = b0v; accB[nt][1] = b1v;
                accB[nt][2] = b0v; accB[nt][3] = b1v;
            }
            gemm_kloop32h(tileh, wtxh, mrow, ncol, lane, accA, accB);
            float p[4] = {0.f, 0.f, 0.f, 0.f};
#pragma unroll
            for (int nt = 0; nt < 4; nt++) {
                int cb = ncol + nt * 8 + tg * 2;
                float w0 = wx2s[cb], w1 = wx2s[cb + 1];
                p[0] += siluf(accA[nt][0]) * w0 + siluf(accA[nt][1]) * w1;
                p[1] += siluf(accA[nt][2]) * w0 + siluf(accA[nt][3]) * w1;
                p[2] += siluf(accB[nt][0]) * w0 + siluf(accB[nt][1]) * w1;
                p[3] += siluf(accB[nt][2]) * w0 + siluf(accB[nt][3]) * w1;
            }
#pragma unroll
            for (int i = 0; i < 4; i++) {
                p[i] += __shfl_xor_sync(0xffffffffu, p[i], 1);
                p[i] += __shfl_xor_sync(0xffffffffu, p[i], 2);
            }
            if (tg == 0) {
                atomicAdd(&sg_cur[mrow + g], p[0]);
                atomicAdd(&sg_cur[mrow + g + 8], p[1]);
                atomicAdd(&sg_cur[mrow + g + 16], p[2]);
                atomicAdd(&sg_cur[mrow + g + 24], p[3]);
            }
        }
        __syncthreads();  // D

        // ---- x scatter (precomputed dir) + stage next tile ----
        if (tid < 128) {
            float gte = sg_cur[tid];
            atomicAdd(&outx[xdi * 3 + 0], xux * gte);
            atomicAdd(&outx[xdi * 3 + 1], xuy * gte);
            atomicAdd(&outx[xdi * 3 + 2], xuz * gte);
            sg_nxt[tid] = bx2v;
        }
        if (hn) {
            *(float4*)&sEA[e_l * EAW + q * 4] = pea;
            if (q == 0) {
                float ss2 = pdx * pdx + pdy * pdy + pdz * pdz;
                float rn = __fdividef(1.0f, sqrtf(ss2) + 1e-9f);
                sEA[e_l * EAW + 16] = sqrtf(ss2 + 1e-9f);
                ((int*)sEA)[e_l * EAW + 17] = psi;
                ((int*)sEA)[e_l * EAW + 18] = pdi;
                sEA[e_l * EAW + 20] = pdx * rn;
                sEA[e_l * EAW + 21] = pdy * rn;
                sEA[e_l * EAW + 22] = pdz * rn;
            }
        }
        __syncthreads();  // E
        pb ^= 1;
    }
}

// ---------------- node update (persistent, 1024 thr, fp16 GEMMs) ------------
__global__ __launch_bounds__(1024, 1) void k_node_upd(
    const float* __restrict__ h, const float* __restrict__ Wh1,
    const float* __restrict__ bh1, const float* __restrict__ Wh2,
    const float* __restrict__ bh2, const float* __restrict__ lng,
    const float* __restrict__ lnb, float* __restrict__ outh) {
    extern __shared__ float sm[];
    float* hr = sm;                        // 128*SP fp32 (residual + LN)
    unsigned* hh = (unsigned*)(hr + 128 * SP);  // 128*SPH h half2 perm
    unsigned* ap = hh + 128 * SPH;         // 128*SPH agg -> tt half2 perm
    unsigned* wt = ap + 128 * SPH;         // 128*SPH weight half2 perm
    float* bh1s = (float*)(wt + 128 * SPH);
    float* bh2s = bh1s + 128;
    float* lngs = bh2s + 128;
    float* lnbs = lngs + 128;
    float* ssum = lnbs + 128;
    float* ssq = ssum + 128;

    int tid = threadIdx.x, lane = tid & 31, warp = tid >> 5;
    if (tid < 128) {
        bh1s[tid] = bh1[tid];
        bh2s[tid] = bh2[tid];
        lngs[tid] = lng[tid];
        lnbs[tid] = lnb[tid];
    }

    int mrow = (warp >> 2) * 16, ncol = (warp & 3) * 32;
    int g = lane >> 2, tg = lane & 3;

    for (int t = blockIdx.x; t < NTILE_N; t += gridDim.x) {
        int n0 = t * 128;
        if (tid < 128) {
            ssum[tid] = 0.f;
            ssq[tid] = 0.f;
        }
#pragma unroll
        for (int v = 0; v < 4; v++) {
            int f = v * 1024 + tid;
            int r = f >> 5, c4 = (f & 31) * 4;
            float4 hv = make_float4(0.f, 0.f, 0.f, 0.f);
            float4 av = make_float4(0.f, 0.f, 0.f, 0.f);
            if (n0 + r < NN) {
                hv = *(const float4*)&h[(n0 + r) * 128 + c4];
                av = *(const float4*)&g_agg[(n0 + r) * 128 + c4];
            }
            *(float4*)&hr[r * SP + c4] = hv;
            int ci = c4 >> 1;
            hh[r * SPH + hslot(ci)] = pack_h2(hv.x, hv.y);
            hh[r * SPH + hslot(ci + 1)] = pack_h2(hv.z, hv.w);
            ap[r * SPH + hslot(ci)] = pack_h2(av.x, av.y);
            ap[r * SPH + hslot(ci + 1)] = pack_h2(av.z, av.w);
        }
        stage_wth1024(wt, Wh1, tid);
        __syncthreads();

        float acc[4][4];
#pragma unroll
        for (int nt = 0; nt < 4; nt++) {
            int cb = ncol + nt * 8 + tg * 2;
            float b0v = bh1s[cb], b1v = bh1s[cb + 1];
            acc[nt][0] = b0v; acc[nt][1] = b1v;
            acc[nt][2] = b0v; acc[nt][3] = b1v;
        }
        gemm_kloop16h(hh, wt, mrow, ncol, lane, acc);
        __syncthreads();
        stage_wth1024(wt, Wh1 + 128 * 128, tid);
        __syncthreads();
        gemm_kloop16h(ap, wt, mrow, ncol, lane, acc);
        __syncthreads();

#pragma unroll
        for (int rr = 0; rr < 2; rr++) {
            int row = mrow + g + rr * 8;
#pragma unroll
            for (int nt = 0; nt < 4; nt++) {
                int c = ncol + nt * 8 + tg * 2;
                ap[row * SPH + hslot(c >> 1)] =
                    pack_h2(siluf(acc[nt][rr * 2 + 0]), siluf(acc[nt][rr * 2 + 1]));
            }
        }
        stage_wth1024(wt, Wh2, tid);
        __syncthreads();

        float acc2[4][4];
#pragma unroll
        for (int nt = 0; nt < 4; nt++) {
            int cb = ncol + nt * 8 + tg * 2;
            float b0v = bh2s[cb], b1v = bh2s[cb + 1];
            acc2[nt][0] = b0v; acc2[nt][1] = b1v;
            acc2[nt][2] = b0v; acc2[nt][3] = b1v;
        }
        gemm_kloop16h(ap, wt, mrow, ncol, lane, acc2);

        float vsum[2] = {0.f, 0.f}, vsq[2] = {0.f, 0.f};
#pragma unroll
        for (int rr = 0; rr < 2; rr++) {
            int row = mrow + g + rr * 8;
#pragma unroll
            for (int nt = 0; nt < 4; nt++) {
                int cb = ncol + nt * 8 + tg * 2;
                float v0 = hr[row * SP + cb] + acc2[nt][rr * 2 + 0];
                float v1 = hr[row * SP + cb + 1] + acc2[nt][rr * 2 + 1];
                acc2[nt][rr * 2 + 0] = v0;
                acc2[nt][rr * 2 + 1] = v1;
                vsum[rr] += v0 + v1;
                vsq[rr] += v0 * v0 + v1 * v1;
            }
        }
#pragma unroll
        for (int i = 0; i < 2; i++) {
            vsum[i] += __shfl_xor_sync(0xffffffffu, vsum[i], 1);
            vsum[i] += __shfl_xor_sync(0xffffffffu, vsum[i], 2);
            vsq[i] += __shfl_xor_sync(0xffffffffu, vsq[i], 1);
            vsq[i] += __shfl_xor_sync(0xffffffffu, vsq[i], 2);
        }
        if (tg == 0) {
            atomicAdd(&ssum[mrow + g], vsum[0]);
            atomicAdd(&ssq[mrow + g], vsq[0]);
            atomicAdd(&ssum[mrow + g + 8], vsum[1]);
            atomicAdd(&ssq[mrow + g + 8], vsq[1]);
        }
        __syncthreads();

#pragma unroll
        for (int rr = 0; rr < 2; rr++) {
            int row = mrow + g + rr * 8;
            float mean = ssum[row] * (1.0f / 128.0f);
            float var = ssq[row] * (1.0f / 128.0f) - mean * mean;
            float rstd = rsqrtf(var + 1e-5f);
            if (n0 + row < NN) {
#pragma unroll
                for (int nt = 0; nt < 4; nt++) {
                    int cb = ncol + nt * 8 + tg * 2;
                    *(float2*)&outh[(n0 + row) * 128 + cb] = make_float2(
                        (acc2[nt][rr * 2 + 0] - mean) * rstd * lngs[cb] + lnbs[cb],
                        (acc2[nt][rr * 2 + 1] - mean) * rstd * lngs[cb + 1] + lnbs[cb + 1]);
                }
            }
        }
        __syncthreads();
    }
}

// ---------------- launcher ---------------------------------------------------
extern "C" void kernel_launch(void* const* d_in, const int* in_sizes, int n_in,
                              void* d_out, int out_size) {
    const float* h = (const float*)d_in[0];
    const float* x = (const float*)d_in[1];
    const void* ei = d_in[2];
    const float* ea = (const float*)d_in[3];
    const float* We1 = (const float*)d_in[4];
    const float* be1 = (const float*)d_in[5];
    const float* We2 = (const float*)d_in[6];
    const float* be2 = (const float*)d_in[7];
    const float* Wh1 = (const float*)d_in[8];
    const float* bh1 = (const float*)d_in[9];
    const float* Wh2 = (const float*)d_in[10];
    const float* bh2 = (const float*)d_in[11];
    const float* Wx1 = (const float*)d_in[12];
    const float* bx1 = (const float*)d_in[13];
    const float* Wx2 = (const float*)d_in[14];
    const float* bx2 = (const float*)d_in[15];
    const float* lng = (const float*)d_in[16];
    const float* lnb = (const float*)d_in[17];

    float* outh = (float*)d_out;
    float* outx = outh + (size_t)NN * 128;

    const int SMEM_EDGE = (3 * 128 * SPH + 128 * EAW + 128 * 16 + 5 * 128 + 256) * 4;  // 134656
    const int SMEM_PRE = (3 * 128 * SPH) * 4;                                           // 110592
    const int SMEM_UPD = (128 * SP + 3 * 128 * SPH + 6 * 128) * 4;                      // 183296
    cudaFuncSetAttribute(k_edge, cudaFuncAttributeMaxDynamicSharedMemorySize, SMEM_EDGE);
    cudaFuncSetAttribute(k_node_pre, cudaFuncAttributeMaxDynamicSharedMemorySize, SMEM_PRE);
    cudaFuncSetAttribute(k_node_upd, cudaFuncAttributeMaxDynamicSharedMemorySize, SMEM_UPD);

    k_detect<<<1, 32>>>(ei);
    k_prep<<<1024, 256>>>(ei, x, outx);
    k_node_pre<<<PGRID, 1024, SMEM_PRE>>>(h, We1);
    k_edge<<<PGRID, 512, SMEM_EDGE>>>(x, ea, We1, be1, We2, be2, Wx1, bx1, Wx2,
                                      bx2, outx);
    k_node_upd<<<PGRID, 1024, SMEM_UPD>>>(h, Wh1, bh1, Wh2, bh2, lng, lnb, outh);
}

// round 16
// speedup vs baseline: 1.0974x; 1.0146x over previous
#include <cuda_runtime.h>
#include <cuda_fp16.h>

#define NN 50000
#define EE 800000
#define SP 136
#define SPH 72   // half2 words per row of fp16 tiles, padded
#define EAW 24   // sEA row: ea[16]|dist|si|di|pad|ux|uy|uz|pad
#define NT2 (EE / 256)
#define NTILE_N ((NN + 127) / 128)
#define PGRID 148

// ---------------- scratch (device globals) ----------------------------------
__device__ int      g_is64;
__device__ int      g_src[EE];
__device__ int      g_dst[EE];
__device__ unsigned g_Ah[NN * 64];   // h @ We1[0:128], half2-packed
__device__ unsigned g_Bh[NN * 64];   // h @ We1[128:256], half2-packed
__device__ float    g_agg[NN * 128]; // segment-sum of m (fp32)

__device__ __forceinline__ float siluf(float v) {
    float t;
    asm("tanh.approx.f32 %0, %1;" : "=f"(t) : "f"(0.5f * v));
    return 0.5f * v * (1.0f + t);
}

__device__ __forceinline__ unsigned f2tf(float v) {
    unsigned u;
    asm("cvt.rna.tf32.f32 %0, %1;" : "=r"(u) : "f"(v));
    return u;
}

// permuted slot of k within its 8-group (tf32): pairs (t, t+4) adjacent
__device__ __forceinline__ int kpos(int k) {
    return (k & ~7) + ((k & 3) * 2 + ((k >> 2) & 1));
}

// permuted slot of half2 index j within its 8-half2 group
__device__ __forceinline__ int hslot(int j) {
    return (j & ~7) + ((j & 3) * 2 + ((j >> 2) & 1));
}

__device__ __forceinline__ unsigned pack_h2(float a, float b) {
    __half2 h = __floats2half2_rn(a, b);
    return *(unsigned*)&h;
}

__device__ __forceinline__ float2 unpack_h2(unsigned u) {
    __half2 h = *(__half2*)&u;
    return __half22float2(h);
}

__device__ __forceinline__ void mma8(float* c, const unsigned* a, const unsigned* b) {
    asm volatile(
        "mma.sync.aligned.m16n8k8.row.col.f32.tf32.tf32.f32 "
        "{%0,%1,%2,%3},{%4,%5,%6,%7},{%8,%9},{%0,%1,%2,%3};"
        : "+f"(c[0]), "+f"(c[1]), "+f"(c[2]), "+f"(c[3])
        : "r"(a[0]), "r"(a[1]), "r"(a[2]), "r"(a[3]), "r"(b[0]), "r"(b[1]));
}

__device__ __forceinline__ void mma16h(float* c, const unsigned* a, const unsigned* b) {
    asm volatile(
        "mma.sync.aligned.m16n8k16.row.col.f32.f16.f16.f32 "
        "{%0,%1,%2,%3},{%4,%5,%6,%7},{%8,%9},{%0,%1,%2,%3};"
        : "+f"(c[0]), "+f"(c[1]), "+f"(c[2]), "+f"(c[3])
        : "r"(a[0]), "r"(a[1]), "r"(a[2]), "r"(a[3]), "r"(b[0]), "r"(b[1]));
}

// ---- stage weight 128x128 -> half2 WT[n][hslot(j)] --------------------------
__device__ __forceinline__ void stage_wth512(unsigned* wt, const float* __restrict__ W,
                                             int tid) {
#pragma unroll
    for (int s = 0; s < 16; s++) {
        int i = s * 512 + tid;
        int n = i & 127, j = i >> 7;
        wt[n * SPH + hslot(j)] = pack_h2(W[(2 * j) * 128 + n], W[(2 * j + 1) * 128 + n]);
    }
}

__device__ __forceinline__ void stage_wth1024(unsigned* wt, const float* __restrict__ W,
                                              int tid) {
#pragma unroll
    for (int s = 0; s < 8; s++) {
        int i = s * 1024 + tid;
        int n = i & 127, j = i >> 7;
        wt[n * SPH + hslot(j)] = pack_h2(W[(2 * j) * 128 + n], W[(2 * j + 1) * 128 + n]);
    }
}

// ---- fp16 k-loop: M=16, N=32, K=128 (node kernels, 32 warps) ---------------
__device__ __forceinline__ void gemm_kloop16h(const unsigned* sA, const unsigned* wt,
                                              int mrow, int ncol, int lane,
                                              float acc[4][4]) {
    int g = lane >> 2, tg = lane & 3;
    const unsigned* a0 = sA + (mrow + g) * SPH + 2 * tg;
    const unsigned* b0 = wt + (ncol + g) * SPH + 2 * tg;
#pragma unroll
    for (int kk = 0; kk < 8; kk++) {
        int k0 = kk * 8;
        uint2 r0 = *(const uint2*)(a0 + k0);
        uint2 r1 = *(const uint2*)(a0 + 8 * SPH + k0);
        unsigned a[4] = {r0.x, r1.x, r0.y, r1.y};
#pragma unroll
        for (int nt = 0; nt < 4; nt++) {
            uint2 bv = *(const uint2*)(b0 + nt * 8 * SPH + k0);
            unsigned bb[2] = {bv.x, bv.y};
            mma16h(acc[nt], a, bb);
        }
    }
}

// ---- fp16 k-loop: M=32, N=32, K=128 (edge kernel) --------------------------
__device__ __forceinline__ void gemm_kloop32h(const unsigned* sA, const unsigned* wt,
                                              int mrow, int ncol, int lane,
                                              float accA[4][4], float accB[4][4]) {
    int g = lane >> 2, tg = lane & 3;
    const unsigned* a0 = sA + (mrow + g) * SPH + 2 * tg;
    const unsigned* b0 = wt + (ncol + g) * SPH + 2 * tg;
#pragma unroll
    for (int kk = 0; kk < 8; kk++) {
        int k0 = kk * 8;
        uint2 r0 = *(const uint2*)(a0 + k0);
        uint2 r1 = *(const uint2*)(a0 + 8 * SPH + k0);
        uint2 r2 = *(const uint2*)(a0 + 16 * SPH + k0);
        uint2 r3 = *(const uint2*)(a0 + 24 * SPH + k0);
        unsigned aA[4] = {r0.x, r1.x, r0.y, r1.y};
        unsigned aB[4] = {r2.x, r3.x, r2.y, r3.y};
#pragma unroll
        for (int nt = 0; nt < 4; nt++) {
            uint2 bv = *(const uint2*)(b0 + nt * 8 * SPH + k0);
            unsigned bb[2] = {bv.x, bv.y};
            mma16h(accA[nt], aA, bb);
            mma16h(accB[nt], aB, bb);
        }
    }
}

// ---------------- index dtype detection -------------------------------------
__global__ void k_detect(const void* ei) {
    if (blockIdx.x == 0 && threadIdx.x == 0) {
        const int* p = (const int*)ei;
        int acc = 0;
        for (int i = 0; i < 64; i++) acc |= p[2 * i + 1];
        g_is64 = (acc == 0) ? 1 : 0;
    }
}

// ---------------- prep: convert indices + zero agg + copy x ------------------
__global__ void k_prep(const void* ei, const float* __restrict__ x,
                       float* __restrict__ outx) {
    int stride = gridDim.x * blockDim.x;
    int base = blockIdx.x * blockDim.x + threadIdx.x;
    if (g_is64) {
        const long long* p = (const long long*)ei;
        for (int e = base; e < EE; e += stride) {
            g_src[e] = (int)p[e];
            g_dst[e] = (int)p[EE + e];
        }
    } else {
        const int* p = (const int*)ei;
        for (int e = base; e < EE; e += stride) {
            g_src[e] = p[e];
            g_dst[e] = p[EE + e];
        }
    }
    for (int i = base; i < NN * 128; i += stride) {
        g_agg[i] = 0.0f;
        if (i < NN * 3) outx[i] = x[i];
    }
}

// ---------------- node pre-GEMM (persistent, 1024 thr, fp16) ----------------
__global__ __launch_bounds__(1024, 1) void k_node_pre(
    const float* __restrict__ h, const float* __restrict__ We1) {
    extern __shared__ float sm[];
    unsigned* hh = (unsigned*)sm;        // 128*SPH half2 perm
    unsigned* wtA = hh + 128 * SPH;
    unsigned* wtB = wtA + 128 * SPH;

    int tid = threadIdx.x, lane = tid & 31, warp = tid >> 5;
    stage_wth1024(wtA, We1, tid);
    stage_wth1024(wtB, We1 + 128 * 128, tid);
    __syncthreads();

    int mrow = (warp >> 2) * 16, ncol = (warp & 3) * 32;
    int g = lane >> 2, tg = lane & 3;

    for (int t = blockIdx.x; t < NTILE_N; t += gridDim.x) {
        int n0 = t * 128;
#pragma unroll
        for (int v = 0; v < 4; v++) {
            int f = v * 1024 + tid;
            int r = f >> 5, c4 = (f & 31) * 4;
            float4 val = make_float4(0.f, 0.f, 0.f, 0.f);
            if (n0 + r < NN) val = *(const float4*)&h[(n0 + r) * 128 + c4];
            int ci = c4 >> 1;
            hh[r * SPH + hslot(ci)] = pack_h2(val.x, val.y);
            hh[r * SPH + hslot(ci + 1)] = pack_h2(val.z, val.w);
        }
        __syncthreads();
#pragma unroll
        for (int half = 0; half < 2; half++) {
            float acc[4][4];
#pragma unroll
            for (int nt = 0; nt < 4; nt++)
#pragma unroll
                for (int l = 0; l < 4; l++) acc[nt][l] = 0.f;
            gemm_kloop16h(hh, half ? wtB : wtA, mrow, ncol, lane, acc);
            unsigned* out = half ? g_Bh : g_Ah;
#pragma unroll
            for (int nt = 0; nt < 4; nt++) {
                int r = mrow + g;
                int cb = ncol + nt * 8 + tg * 2;
                if (n0 + r < NN)
                    out[(n0 + r) * 64 + (cb >> 1)] = pack_h2(acc[nt][0], acc[nt][1]);
                if (n0 + r + 8 < NN)
                    out[(n0 + r + 8) * 64 + (cb >> 1)] = pack_h2(acc[nt][2], acc[nt][3]);
            }
        }
        __syncthreads();
    }
}

// ---------------- fused edge kernel (persistent, 512 thr, 256-edge tiles) ---
__global__ __launch_bounds__(512, 1) void k_edge(
    const float* __restrict__ x, const float* __restrict__ ea,
    const float* __restrict__ We1, const float* __restrict__ be1,
    const float* __restrict__ We2, const float* __restrict__ be2,
    const float* __restrict__ Wx1, const float* __restrict__ bx1,
    const float* __restrict__ Wx2, const float* __restrict__ bx2,
    float* __restrict__ outx) {
    extern __shared__ float sm[];
    unsigned* tileh = (unsigned*)sm;        // 256*SPH half2 (s -> mm)
    unsigned* wt2h = tileh + 256 * SPH;     // We2^T fp16 perm
    unsigned* wtxh = wt2h + 128 * SPH;      // Wx1^T fp16 perm
    float* sEA = (float*)(wtxh + 128 * SPH);  // 256*EAW
    float* wtE = sEA + 256 * EAW;           // 128*16: edge-attr block, tf32 perm
    float* wds = wtE + 128 * 16;
    float* be1s = wds + 128;
    float* be2s = be1s + 128;
    float* bx1s = be2s + 128;
    float* wx2s = bx1s + 128;
    float* sgate = wx2s + 128;              // 2*256 (double-buffered)

    int tid = threadIdx.x, lane = tid & 31, warp = tid >> 5;

    // ---- one-time staging ----
    stage_wth512(wt2h, We2, tid);
    stage_wth512(wtxh, Wx1, tid);
#pragma unroll
    for (int s = 0; s < 4; s++) {
        int i = s * 512 + tid;
        int n = i & 127, k = i >> 7;
        wtE[n * 16 + kpos(k)] = __uint_as_float(f2tf(We1[(256 + k) * 128 + n]));
    }
    if (tid < 128) {
        wds[tid] = We1[272 * 128 + tid];
        be1s[tid] = be1[tid];
        be2s[tid] = be2[tid];
        bx1s[tid] = bx1[tid];
        wx2s[tid] = Wx2[tid];
    }
    float bx2v = bx2[0];

    // warp tile: M=32 per chunk, N=32; chunks at rows +0 and +128
    int mrow = (warp & 3) * 32, ncol = (warp >> 2) * 32;
    int g = lane >> 2, tg = lane & 3;
    int e_l = tid >> 1, q = tid & 1;   // 2 threads per edge row for staging

    // ---- stage first tile ----
    {
        int e = blockIdx.x * 256 + e_l;
        *(float4*)&sEA[e_l * EAW + q * 8] = *(const float4*)&ea[e * 16 + q * 8];
        *(float4*)&sEA[e_l * EAW + q * 8 + 4] = *(const float4*)&ea[e * 16 + q * 8 + 4];
        if (q == 0) {
            int si = g_src[e], di = g_dst[e];
            float dx = x[di * 3 + 0] - x[si * 3 + 0];
            float dy = x[di * 3 + 1] - x[si * 3 + 1];
            float dz = x[di * 3 + 2] - x[si * 3 + 2];
            float ss2 = dx * dx + dy * dy + dz * dz;
            float rn = __fdividef(1.0f, sqrtf(ss2) + 1e-9f);
            sEA[e_l * EAW + 16] = sqrtf(ss2 + 1e-9f);
            ((int*)sEA)[e_l * EAW + 17] = si;
            ((int*)sEA)[e_l * EAW + 18] = di;
            sEA[e_l * EAW + 20] = dx * rn;
            sEA[e_l * EAW + 21] = dy * rn;
            sEA[e_l * EAW + 22] = dz * rn;
        }
        if (tid < 256) sgate[tid] = bx2v;
    }
    __syncthreads();

    int pb = 0;
    for (int t = blockIdx.x; t < NT2; t += PGRID) {
        float* sg_cur = sgate + pb * 256;
        float* sg_nxt = sgate + (pb ^ 1) * 256;
        int tn = t + PGRID;
        bool hn = tn < NT2;

        // ---- phase1 (both chunks): ea-GEMM + gather + silu -> tileh --------
#pragma unroll
        for (int ch = 0; ch < 2; ch++) {
            int cb = ch * 128;
            float accA[4][4], accB[4][4];
#pragma unroll
            for (int nt = 0; nt < 4; nt++)
#pragma unroll
                for (int l = 0; l < 4; l++) { accA[nt][l] = 0.f; accB[nt][l] = 0.f; }
            const float* a0p = sEA + (cb + mrow + g) * EAW + tg;
            const float* b0p = wtE + (ncol + g) * 16 + 2 * tg;
#pragma unroll
            for (int kk = 0; kk < 2; kk++) {
                int k0 = kk * 8;
                unsigned aA[4], aB[4];
                aA[0] = f2tf(a0p[k0]);
                aA[1] = f2tf(a0p[8 * EAW + k0]);
                aA[2] = f2tf(a0p[k0 + 4]);
                aA[3] = f2tf(a0p[8 * EAW + k0 + 4]);
                aB[0] = f2tf(a0p[16 * EAW + k0]);
                aB[1] = f2tf(a0p[24 * EAW + k0]);
                aB[2] = f2tf(a0p[16 * EAW + k0 + 4]);
                aB[3] = f2tf(a0p[24 * EAW + k0 + 4]);
#pragma unroll
                for (int nt = 0; nt < 4; nt++) {
                    float2 b = *(const float2*)(b0p + nt * 8 * 16 + k0);
                    unsigned bb[2] = {__float_as_uint(b.x), __float_as_uint(b.y)};
                    mma8(accA[nt], aA, bb);
                    mma8(accB[nt], aB, bb);
                }
            }
#pragma unroll
            for (int rr = 0; rr < 4; rr++) {
                int row = cb + mrow + g + rr * 8;
                float* ac = (rr < 2) ? &accA[0][0] : &accB[0][0];
                int jo = (rr & 1) * 2;
                int si = ((const int*)sEA)[row * EAW + 17];
                int di = ((const int*)sEA)[row * EAW + 18];
                float dist = sEA[row * EAW + 16];
#pragma unroll
                for (int nt = 0; nt < 4; nt++) {
                    int c = ncol + nt * 8 + tg * 2;
                    float2 a2 = unpack_h2(g_Ah[si * 64 + (c >> 1)]);
                    float2 b2 = unpack_h2(g_Bh[di * 64 + (c >> 1)]);
                    float v0 = ac[nt * 4 + jo + 0] + dist * wds[c] + be1s[c] + a2.x + b2.x;
                    float v1 = ac[nt * 4 + jo + 1] + dist * wds[c + 1] + be1s[c + 1] +
                               a2.y + b2.y;
                    tileh[row * SPH + hslot(c >> 1)] = pack_h2(siluf(v0), siluf(v1));
                }
            }
        }
        __syncthreads();  // A

        // ---- GEMM1 chunk0 + agg scatter ----
        float accmA[4][4], accmB[4][4];
#pragma unroll
        for (int nt = 0; nt < 4; nt++) {
            int cb2 = ncol + nt * 8 + tg * 2;
            float b0v = be2s[cb2], b1v = be2s[cb2 + 1];
            accmA[nt][0] = b0v; accmA[nt][1] = b1v;
            accmA[nt][2] = b0v; accmA[nt][3] = b1v;
            accmB[nt][0] = b0v; accmB[nt][1] = b1v;
            accmB[nt][2] = b0v; accmB[nt][3] = b1v;
        }
        gemm_kloop32h(tileh, wt2h, mrow, ncol, lane, accmA, accmB);
#pragma unroll
        for (int rr = 0; rr < 4; rr++) {
            int row = mrow + g + rr * 8;
            const float* ac = (rr < 2) ? &accmA[0][0] : &accmB[0][0];
            int jo = (rr & 1) * 2;
            int di = ((const int*)sEA)[row * EAW + 18];
#pragma unroll
            for (int nt = 0; nt < 4; nt++) {
                float v0 = ac[nt * 4 + jo + 0];
                float v1 = ac[nt * 4 + jo + 1];
                float o0 = __shfl_xor_sync(0xffffffffu, v0, 1);
                float o1 = __shfl_xor_sync(0xffffffffu, v1, 1);
                if ((tg & 1) == 0) {
                    int c = ncol + nt * 8 + tg * 2;
                    asm volatile("red.global.add.v4.f32 [%0], {%1,%2,%3,%4};"
                                 :: "l"(&g_agg[di * 128 + c]),
                                    "f"(v0), "f"(v1), "f"(o0), "f"(o1)
                                 : "memory");
                }
            }
        }
        __syncthreads();  // B0 (all warps done reading chunk0 s)

        // store mm chunk0, then GEMM1 chunk1 (reads chunk1 s, untouched)
#pragma unroll
        for (int rr = 0; rr < 4; rr++) {
            int row = mrow + g + rr * 8;
            const float* ac = (rr < 2) ? &accmA[0][0] : &accmB[0][0];
            int jo = (rr & 1) * 2;
#pragma unroll
            for (int nt = 0; nt < 4; nt++) {
                int c = ncol + nt * 8 + tg * 2;
                tileh[row * SPH + hslot(c >> 1)] =
                    pack_h2(ac[nt * 4 + jo + 0], ac[nt * 4 + jo + 1]);
            }
        }
#pragma unroll
        for (int nt = 0; nt < 4; nt++) {
            int cb2 = ncol + nt * 8 + tg * 2;
            float b0v = be2s[cb2], b1v = be2s[cb2 + 1];
            accmA[nt][0] = b0v; accmA[nt][1] = b1v;
            accmA[nt][2] = b0v; accmA[nt][3] = b1v;
            accmB[nt][0] = b0v; accmB[nt][1] = b1v;
            accmB[nt][2] = b0v; accmB[nt][3] = b1v;
        }
        gemm_kloop32h(tileh, wt2h, 128 + mrow, ncol, lane, accmA, accmB);
#pragma unroll
        for (int rr = 0; rr < 4; rr++) {
            int row = 128 + mrow + g + rr * 8;
            const float* ac = (rr < 2) ? &accmA[0][0] : &accmB[0][0];
            int jo = (rr & 1) * 2;
            int di = ((const int*)sEA)[row * EAW + 18];
#pragma unroll
            for (int nt = 0; nt < 4; nt++) {
                float v0 = ac[nt * 4 + jo + 0];
                float v1 = ac[nt * 4 + jo + 1];
                float o0 = __shfl_xor_sync(0xffffffffu, v0, 1);
                float o1 = __shfl_xor_sync(0xffffffffu, v1, 1);
                if ((tg & 1) == 0) {
                    int c = ncol + nt * 8 + tg * 2;
                    asm volatile("red.global.add.v4.f32 [%0], {%1,%2,%3,%4};"
                                 :: "l"(&g_agg[di * 128 + c]),
                                    "f"(v0), "f"(v1), "f"(o0), "f"(o1)
                                 : "memory");
                }
            }
        }
        __syncthreads();  // B1 (all warps done reading chunk1 s; mm0 visible)

        // store mm chunk1
#pragma unroll
        for (int rr = 0; rr < 4; rr++) {
            int row = 128 + mrow + g + rr * 8;
            const float* ac = (rr < 2) ? &accmA[0][0] : &accmB[0][0];
            int jo = (rr & 1) * 2;
#pragma unroll
            for (int nt = 0; nt < 4; nt++) {
                int c = ncol + nt * 8 + tg * 2;
                tileh[row * SPH + hslot(c >> 1)] =
                    pack_h2(ac[nt * 4 + jo + 0], ac[nt * 4 + jo + 1]);
            }
        }

        // ---- prefetch next tile (regs) ----
        float4 pea0, pea1;
        int psi = 0, pdi = 0;
        float pdx = 0.f, pdy = 0.f, pdz = 0.f;
        if (hn) {
            int e = tn * 256 + e_l;
            pea0 = *(const float4*)&ea[e * 16 + q * 8];
            pea1 = *(const float4*)&ea[e * 16 + q * 8 + 4];
            if (q == 0) {
                psi = g_src[e];
                pdi = g_dst[e];
                pdx = x[pdi * 3 + 0] - x[psi * 3 + 0];
                pdy = x[pdi * 3 + 1] - x[psi * 3 + 1];
                pdz = x[pdi * 3 + 2] - x[psi * 3 + 2];
            }
        }
        int xdi = 0;
        float xux = 0.f, xuy = 0.f, xuz = 0.f;
        if (tid < 256) {
            xdi = ((const int*)sEA)[tid * EAW + 18];
            xux = sEA[tid * EAW + 20];
            xuy = sEA[tid * EAW + 21];
            xuz = sEA[tid * EAW + 22];
        }

        // ---- GEMM2 chunk0 (mm0 visible since B1) ----
        {
            float accA[4][4], accB[4][4];
#pragma unroll
            for (int nt = 0; nt < 4; nt++) {
                int cb2 = ncol + nt * 8 + tg * 2;
                float b0v = bx1s[cb2], b1v = bx1s[cb2 + 1];
                accA[nt][0] = b0v; accA[nt][1] = b1v;
                accA[nt][2] = b0v; accA[nt][3] = b1v;
                accB[nt][0] = b0v; accB[nt][1] = b1v;
                accB[nt][2] = b0v; accB[nt][3] = b1v;
            }
            gemm_kloop32h(tileh, wtxh, mrow, ncol, lane, accA, accB);
            float p[4] = {0.f, 0.f, 0.f, 0.f};
#pragma unroll
            for (int nt = 0; nt < 4; nt++) {
                int cb2 = ncol + nt * 8 + tg * 2;
                float w0 = wx2s[cb2], w1 = wx2s[cb2 + 1];
                p[0] += siluf(accA[nt][0]) * w0 + siluf(accA[nt][1]) * w1;
                p[1] += siluf(accA[nt][2]) * w0 + siluf(accA[nt][3]) * w1;
                p[2] += siluf(accB[nt][0]) * w0 + siluf(accB[nt][1]) * w1;
                p[3] += siluf(accB[nt][2]) * w0 + siluf(accB[nt][3]) * w1;
            }
#pragma unroll
            for (int i = 0; i < 4; i++) {
                p[i] += __shfl_xor_sync(0xffffffffu, p[i], 1);
                p[i] += __shfl_xor_sync(0xffffffffu, p[i], 2);
            }
            if (tg == 0) {
                atomicAdd(&sg_cur[mrow + g], p[0]);
                atomicAdd(&sg_cur[mrow + g + 8], p[1]);
                atomicAdd(&sg_cur[mrow + g + 16], p[2]);
                atomicAdd(&sg_cur[mrow + g + 24], p[3]);
            }
        }
        __syncthreads();  // C (mm1 visible for GEMM2 chunk1)

        // ---- GEMM2 chunk1 ----
        {
            float accA[4][4], accB[4][4];
#pragma unroll
            for (int nt = 0; nt < 4; nt++) {
                int cb2 = ncol + nt * 8 + tg * 2;
                float b0v = bx1s[cb2], b1v = bx1s[cb2 + 1];
                accA[nt][0] = b0v; accA[nt][1] = b1v;
                accA[nt][2] = b0v; accA[nt][3] = b1v;
                accB[nt][0] = b0v; accB[nt][1] = b1v;
                accB[nt][2] = b0v; accB[nt][3] = b1v;
            }
            gemm_kloop32h(tileh, wtxh, 128 + mrow, ncol, lane, accA, accB);
            float p[4] = {0.f, 0.f, 0.f, 0.f};
#pragma unroll
            for (int nt = 0; nt < 4; nt++) {
                int cb2 = ncol + nt * 8 + tg * 2;
                float w0 = wx2s[cb2], w1 = wx2s[cb2 + 1];
                p[0] += siluf(accA[nt][0]) * w0 + siluf(accA[nt][1]) * w1;
                p[1] += siluf(accA[nt][2]) * w0 + siluf(accA[nt][3]) * w1;
                p[2] += siluf(accB[nt][0]) * w0 + siluf(accB[nt][1]) * w1;
                p[3] += siluf(accB[nt][2]) * w0 + siluf(accB[nt][3]) * w1;
            }
#pragma unroll
            for (int i = 0; i < 4; i++) {
                p[i] += __shfl_xor_sync(0xffffffffu, p[i], 1);
                p[i] += __shfl_xor_sync(0xffffffffu, p[i], 2);
            }
            if (tg == 0) {
                atomicAdd(&sg_cur[128 + mrow + g], p[0]);
                atomicAdd(&sg_cur[128 + mrow + g + 8], p[1]);
                atomicAdd(&sg_cur[128 + mrow + g + 16], p[2]);
                atomicAdd(&sg_cur[128 + mrow + g + 24], p[3]);
            }
        }
        __syncthreads();  // D

        // ---- x scatter (precomputed dir) + stage next tile ----
        if (tid < 256) {
            float gte = sg_cur[tid];
            atomicAdd(&outx[xdi * 3 + 0], xux * gte);
            atomicAdd(&outx[xdi * 3 + 1], xuy * gte);
            atomicAdd(&outx[xdi * 3 + 2], xuz * gte);
            sg_nxt[tid] = bx2v;
        }
        if (hn) {
            *(float4*)&sEA[e_l * EAW + q * 8] = pea0;
            *(float4*)&sEA[e_l * EAW + q * 8 + 4] = pea1;
            if (q == 0) {
                float ss2 = pdx * pdx + pdy * pdy + pdz * pdz;
                float rn = __fdividef(1.0f, sqrtf(ss2) + 1e-9f);
                sEA[e_l * EAW + 16] = sqrtf(ss2 + 1e-9f);
                ((int*)sEA)[e_l * EAW + 17] = psi;
                ((int*)sEA)[e_l * EAW + 18] = pdi;
                sEA[e_l * EAW + 20] = pdx * rn;
                sEA[e_l * EAW + 21] = pdy * rn;
                sEA[e_l * EAW + 22] = pdz * rn;
            }
        }
        __syncthreads();  // E
        pb ^= 1;
    }
}

// ---------------- node update (persistent, 1024 thr, fp16 GEMMs) ------------
__global__ __launch_bounds__(1024, 1) void k_node_upd(
    const float* __restrict__ h, const float* __restrict__ Wh1,
    const float* __restrict__ bh1, const float* __restrict__ Wh2,
    const float* __restrict__ bh2, const float* __restrict__ lng,
    const float* __restrict__ lnb, float* __restrict__ outh) {
    extern __shared__ float sm[];
    float* hr = sm;                        // 128*SP fp32 (residual + LN)
    unsigned* hh = (unsigned*)(hr + 128 * SP);  // 128*SPH h half2 perm
    unsigned* ap = hh + 128 * SPH;         // 128*SPH agg -> tt half2 perm
    unsigned* wt = ap + 128 * SPH;         // 128*SPH weight half2 perm
    float* bh1s = (float*)(wt + 128 * SPH);
    float* bh2s = bh1s + 128;
    float* lngs = bh2s + 128;
    float* lnbs = lngs + 128;
    float* ssum = lnbs + 128;
    float* ssq = ssum + 128;

    int tid = threadIdx.x, lane = tid & 31, warp = tid >> 5;
    if (tid < 128) {
        bh1s[tid] = bh1[tid];
        bh2s[tid] = bh2[tid];
        lngs[tid] = lng[tid];
        lnbs[tid] = lnb[tid];
    }

    int mrow = (warp >> 2) * 16, ncol = (warp & 3) * 32;
    int g = lane >> 2, tg = lane & 3;

    for (int t = blockIdx.x; t < NTILE_N; t += gridDim.x) {
        int n0 = t * 128;
        if (tid < 128) {
            ssum[tid] = 0.f;
            ssq[tid] = 0.f;
        }
#pragma unroll
        for (int v = 0; v < 4; v++) {
            int f = v * 1024 + tid;
            int r = f >> 5, c4 = (f & 31) * 4;
            float4 hv = make_float4(0.f, 0.f, 0.f, 0.f);
            float4 av = make_float4(0.f, 0.f, 0.f, 0.f);
            if (n0 + r < NN) {
                hv = *(const float4*)&h[(n0 + r) * 128 + c4];
                av = *(const float4*)&g_agg[(n0 + r) * 128 + c4];
            }
            *(float4*)&hr[r * SP + c4] = hv;
            int ci = c4 >> 1;
            hh[r * SPH + hslot(ci)] = pack_h2(hv.x, hv.y);
            hh[r * SPH + hslot(ci + 1)] = pack_h2(hv.z, hv.w);
            ap[r * SPH + hslot(ci)] = pack_h2(av.x, av.y);
            ap[r * SPH + hslot(ci + 1)] = pack_h2(av.z, av.w);
        }
        stage_wth1024(wt, Wh1, tid);
        __syncthreads();

        float acc[4][4];
#pragma unroll
        for (int nt = 0; nt < 4; nt++) {
            int cb = ncol + nt * 8 + tg * 2;
            float b0v = bh1s[cb], b1v = bh1s[cb + 1];
            acc[nt][0] = b0v; acc[nt][1] = b1v;
            acc[nt][2] = b0v; acc[nt][3] = b1v;
        }
        gemm_kloop16h(hh, wt, mrow, ncol, lane, acc);
        __syncthreads();
        stage_wth1024(wt, Wh1 + 128 * 128, tid);
        __syncthreads();
        gemm_kloop16h(ap, wt, mrow, ncol, lane, acc);
        __syncthreads();

#pragma unroll
        for (int rr = 0; rr < 2; rr++) {
            int row = mrow + g + rr * 8;
#pragma unroll
            for (int nt = 0; nt < 4; nt++) {
                int c = ncol + nt * 8 + tg * 2;
                ap[row * SPH + hslot(c >> 1)] =
                    pack_h2(siluf(acc[nt][rr * 2 + 0]), siluf(acc[nt][rr * 2 + 1]));
            }
        }
        stage_wth1024(wt, Wh2, tid);
        __syncthreads();

        float acc2[4][4];
#pragma unroll
        for (int nt = 0; nt < 4; nt++) {
            int cb = ncol + nt * 8 + tg * 2;
            float b0v = bh2s[cb], b1v = bh2s[cb + 1];
            acc2[nt][0] = b0v; acc2[nt][1] = b1v;
            acc2[nt][2] = b0v; acc2[nt][3] = b1v;
        }
        gemm_kloop16h(ap, wt, mrow, ncol, lane, acc2);

        float vsum[2] = {0.f, 0.f}, vsq[2] = {0.f, 0.f};
#pragma unroll
        for (int rr = 0; rr < 2; rr++) {
            int row = mrow + g + rr * 8;
#pragma unroll
            for (int nt = 0; nt < 4; nt++) {
                int cb = ncol + nt * 8 + tg * 2;
                float v0 = hr[row * SP + cb] + acc2[nt][rr * 2 + 0];
                float v1 = hr[row * SP + cb + 1] + acc2[nt][rr * 2 + 1];
                acc2[nt][rr * 2 + 0] = v0;
                acc2[nt][rr * 2 + 1] = v1;
                vsum[rr] += v0 + v1;
                vsq[rr] += v0 * v0 + v1 * v1;
            }
        }
#pragma unroll
        for (int i = 0; i < 2; i++) {
            vsum[i] += __shfl_xor_sync(0xffffffffu, vsum[i], 1);
            vsum[i] += __shfl_xor_sync(0xffffffffu, vsum[i], 2);
            vsq[i] += __shfl_xor_sync(0xffffffffu, vsq[i], 1);
            vsq[i] += __shfl_xor_sync(0xffffffffu, vsq[i], 2);
        }
        if (tg == 0) {
            atomicAdd(&ssum[mrow + g], vsum[0]);
            atomicAdd(&ssq[mrow + g], vsq[0]);
            atomicAdd(&ssum[mrow + g + 8], vsum[1]);
            atomicAdd(&ssq[mrow + g + 8], vsq[1]);
        }
        __syncthreads();

#pragma unroll
        for (int rr = 0; rr < 2; rr++) {
            int row = mrow + g + rr * 8;
            float mean = ssum[row] * (1.0f / 128.0f);
            float var = ssq[row] * (1.0f / 128.0f) - mean * mean;
            float rstd = rsqrtf(var + 1e-5f);
            if (n0 + row < NN) {
#pragma unroll
                for (int nt = 0; nt < 4; nt++) {
                    int cb = ncol + nt * 8 + tg * 2;
                    *(float2*)&outh[(n0 + row) * 128 + cb] = make_float2(
                        (acc2[nt][rr * 2 + 0] - mean) * rstd * lngs[cb] + lnbs[cb],
                        (acc2[nt][rr * 2 + 1] - mean) * rstd * lngs[cb + 1] + lnbs[cb + 1]);
                }
            }
        }
        __syncthreads();
    }
}

// ---------------- launcher ---------------------------------------------------
extern "C" void kernel_launch(void* const* d_in, const int* in_sizes, int n_in,
                              void* d_out, int out_size) {
    const float* h = (const float*)d_in[0];
    const float* x = (const float*)d_in[1];
    const void* ei = d_in[2];
    const float* ea = (const float*)d_in[3];
    const float* We1 = (const float*)d_in[4];
    const float* be1 = (const float*)d_in[5];
    const float* We2 = (const float*)d_in[6];
    const float* be2 = (const float*)d_in[7];
    const float* Wh1 = (const float*)d_in[8];
    const float* bh1 = (const float*)d_in[9];
    const float* Wh2 = (const float*)d_in[10];
    const float* bh2 = (const float*)d_in[11];
    const float* Wx1 = (const float*)d_in[12];
    const float* bx1 = (const float*)d_in[13];
    const float* Wx2 = (const float*)d_in[14];
    const float* bx2 = (const float*)d_in[15];
    const float* lng = (const float*)d_in[16];
    const float* lnb = (const float*)d_in[17];

    float* outh = (float*)d_out;
    float* outx = outh + (size_t)NN * 128;

    const int SMEM_EDGE =
        (256 * SPH + 2 * 128 * SPH + 256 * EAW + 128 * 16 + 5 * 128 + 512) * 4;  // 184832
    const int SMEM_PRE = (3 * 128 * SPH) * 4;                                     // 110592
    const int SMEM_UPD = (128 * SP + 3 * 128 * SPH + 6 * 128) * 4;                // 183296
    cudaFuncSetAttribute(k_edge, cudaFuncAttributeMaxDynamicSharedMemorySize, SMEM_EDGE);
    cudaFuncSetAttribute(k_node_pre, cudaFuncAttributeMaxDynamicSharedMemorySize, SMEM_PRE);
    cudaFuncSetAttribute(k_node_upd, cudaFuncAttributeMaxDynamicSharedMemorySize, SMEM_UPD);

    k_detect<<<1, 32>>>(ei);
    k_prep<<<1024, 256>>>(ei, x, outx);
    k_node_pre<<<PGRID, 1024, SMEM_PRE>>>(h, We1);
    k_edge<<<PGRID, 512, SMEM_EDGE>>>(x, ea, We1, be1, We2, be2, Wx1, bx1, Wx2,
                                      bx2, outx);
    k_node_upd<<<PGRID, 1024, SMEM_UPD>>>(h, Wh1, bh1, Wh2, bh2, lng, lnb, outh);
}

// round 17
// speedup vs baseline: 1.1223x; 1.0227x over previous
#include <cuda_runtime.h>
#include <cuda_fp16.h>

#define NN 50000
#define EE 800000
#define SP 136
#define SPH 72   // half2 words per row of fp16 tiles, padded
#define EAW 24   // sEA row: ea[16]|dist|si|di|pad|ux|uy|uz|pad
#define NT2 (EE / 256)
#define NTILE_N ((NN + 127) / 128)
#define PGRID 148

// ---------------- scratch (device globals) ----------------------------------
__device__ int      g_is64;
__device__ int      g_src[EE];
__device__ int      g_dst[EE];
__device__ unsigned g_Ah[NN * 64];   // h @ We1[0:128], half2-packed
__device__ unsigned g_Bh[NN * 64];   // h @ We1[128:256], half2-packed
__device__ float    g_agg[NN * 128]; // segment-sum of m (fp32)

__device__ __forceinline__ float siluf(float v) {
    float t;
    asm("tanh.approx.f32 %0, %1;" : "=f"(t) : "f"(0.5f * v));
    return 0.5f * v * (1.0f + t);
}

__device__ __forceinline__ unsigned f2tf(float v) {
    unsigned u;
    asm("cvt.rna.tf32.f32 %0, %1;" : "=r"(u) : "f"(v));
    return u;
}

// permuted slot of k within its 8-group (tf32): pairs (t, t+4) adjacent
__device__ __forceinline__ int kpos(int k) {
    return (k & ~7) + ((k & 3) * 2 + ((k >> 2) & 1));
}

// permuted slot of half2 index j within its 8-half2 group
__device__ __forceinline__ int hslot(int j) {
    return (j & ~7) + ((j & 3) * 2 + ((j >> 2) & 1));
}

__device__ __forceinline__ unsigned pack_h2(float a, float b) {
    __half2 h = __floats2half2_rn(a, b);
    return *(unsigned*)&h;
}

__device__ __forceinline__ float2 unpack_h2(unsigned u) {
    __half2 h = *(__half2*)&u;
    return __half22float2(h);
}

__device__ __forceinline__ void mma8(float* c, const unsigned* a, const unsigned* b) {
    asm volatile(
        "mma.sync.aligned.m16n8k8.row.col.f32.tf32.tf32.f32 "
        "{%0,%1,%2,%3},{%4,%5,%6,%7},{%8,%9},{%0,%1,%2,%3};"
        : "+f"(c[0]), "+f"(c[1]), "+f"(c[2]), "+f"(c[3])
        : "r"(a[0]), "r"(a[1]), "r"(a[2]), "r"(a[3]), "r"(b[0]), "r"(b[1]));
}

__device__ __forceinline__ void mma16h(float* c, const unsigned* a, const unsigned* b) {
    asm volatile(
        "mma.sync.aligned.m16n8k16.row.col.f32.f16.f16.f32 "
        "{%0,%1,%2,%3},{%4,%5,%6,%7},{%8,%9},{%0,%1,%2,%3};"
        : "+f"(c[0]), "+f"(c[1]), "+f"(c[2]), "+f"(c[3])
        : "r"(a[0]), "r"(a[1]), "r"(a[2]), "r"(a[3]), "r"(b[0]), "r"(b[1]));
}

// ---- stage weight 128x128 -> half2 WT[n][hslot(j)] --------------------------
__device__ __forceinline__ void stage_wth512(unsigned* wt, const float* __restrict__ W,
                                             int tid) {
#pragma unroll
    for (int s = 0; s < 16; s++) {
        int i = s * 512 + tid;
        int n = i & 127, j = i >> 7;
        wt[n * SPH + hslot(j)] = pack_h2(W[(2 * j) * 128 + n], W[(2 * j + 1) * 128 + n]);
    }
}

__device__ __forceinline__ void stage_wth1024(unsigned* wt, const float* __restrict__ W,
                                              int tid) {
#pragma unroll
    for (int s = 0; s < 8; s++) {
        int i = s * 1024 + tid;
        int n = i & 127, j = i >> 7;
        wt[n * SPH + hslot(j)] = pack_h2(W[(2 * j) * 128 + n], W[(2 * j + 1) * 128 + n]);
    }
}

// ---- fp16 k-loop: M=16, N=32, K=128 (node kernels, 32 warps) ---------------
__device__ __forceinline__ void gemm_kloop16h(const unsigned* sA, const unsigned* wt,
                                              int mrow, int ncol, int lane,
                                              float acc[4][4]) {
    int g = lane >> 2, tg = lane & 3;
    const unsigned* a0 = sA + (mrow + g) * SPH + 2 * tg;
    const unsigned* b0 = wt + (ncol + g) * SPH + 2 * tg;
#pragma unroll
    for (int kk = 0; kk < 8; kk++) {
        int k0 = kk * 8;
        uint2 r0 = *(const uint2*)(a0 + k0);
        uint2 r1 = *(const uint2*)(a0 + 8 * SPH + k0);
        unsigned a[4] = {r0.x, r1.x, r0.y, r1.y};
#pragma unroll
        for (int nt = 0; nt < 4; nt++) {
            uint2 bv = *(const uint2*)(b0 + nt * 8 * SPH + k0);
            unsigned bb[2] = {bv.x, bv.y};
            mma16h(acc[nt], a, bb);
        }
    }
}

// ---- fp16 k-loop: M=32, N=32, K=128 (edge kernel) --------------------------
__device__ __forceinline__ void gemm_kloop32h(const unsigned* sA, const unsigned* wt,
                                              int mrow, int ncol, int lane,
                                              float accA[4][4], float accB[4][4]) {
    int g = lane >> 2, tg = lane & 3;
    const unsigned* a0 = sA + (mrow + g) * SPH + 2 * tg;
    const unsigned* b0 = wt + (ncol + g) * SPH + 2 * tg;
#pragma unroll
    for (int kk = 0; kk < 8; kk++) {
        int k0 = kk * 8;
        uint2 r0 = *(const uint2*)(a0 + k0);
        uint2 r1 = *(const uint2*)(a0 + 8 * SPH + k0);
        uint2 r2 = *(const uint2*)(a0 + 16 * SPH + k0);
        uint2 r3 = *(const uint2*)(a0 + 24 * SPH + k0);
        unsigned aA[4] = {r0.x, r1.x, r0.y, r1.y};
        unsigned aB[4] = {r2.x, r3.x, r2.y, r3.y};
#pragma unroll
        for (int nt = 0; nt < 4; nt++) {
            uint2 bv = *(const uint2*)(b0 + nt * 8 * SPH + k0);
            unsigned bb[2] = {bv.x, bv.y};
            mma16h(accA[nt], aA, bb);
            mma16h(accB[nt], aB, bb);
        }
    }
}

// ---------------- index dtype detection -------------------------------------
__global__ void k_detect(const void* ei) {
    if (blockIdx.x == 0 && threadIdx.x == 0) {
        const int* p = (const int*)ei;
        int acc = 0;
        for (int i = 0; i < 64; i++) acc |= p[2 * i + 1];
        g_is64 = (acc == 0) ? 1 : 0;
    }
}

// ---------------- prep: convert indices + zero agg + copy x ------------------
__global__ void k_prep(const void* ei, const float* __restrict__ x,
                       float* __restrict__ outx) {
    int stride = gridDim.x * blockDim.x;
    int base = blockIdx.x * blockDim.x + threadIdx.x;
    if (g_is64) {
        const long long* p = (const long long*)ei;
        for (int e = base; e < EE; e += stride) {
            g_src[e] = (int)p[e];
            g_dst[e] = (int)p[EE + e];
        }
    } else {
        const int* p = (const int*)ei;
        for (int e = base; e < EE; e += stride) {
            g_src[e] = p[e];
            g_dst[e] = p[EE + e];
        }
    }
    for (int i = base; i < NN * 128; i += stride) {
        g_agg[i] = 0.0f;
        if (i < NN * 3) outx[i] = x[i];
    }
}

// ---------------- node pre-GEMM (persistent, 1024 thr, fp16) ----------------
__global__ __launch_bounds__(1024, 1) void k_node_pre(
    const float* __restrict__ h, const float* __restrict__ We1) {
    extern __shared__ float sm[];
    unsigned* hh = (unsigned*)sm;        // 128*SPH half2 perm
    unsigned* wtA = hh + 128 * SPH;
    unsigned* wtB = wtA + 128 * SPH;

    int tid = threadIdx.x, lane = tid & 31, warp = tid >> 5;
    stage_wth1024(wtA, We1, tid);
    stage_wth1024(wtB, We1 + 128 * 128, tid);
    __syncthreads();

    int mrow = (warp >> 2) * 16, ncol = (warp & 3) * 32;
    int g = lane >> 2, tg = lane & 3;

    for (int t = blockIdx.x; t < NTILE_N; t += gridDim.x) {
        int n0 = t * 128;
#pragma unroll
        for (int v = 0; v < 4; v++) {
            int f = v * 1024 + tid;
            int r = f >> 5, c4 = (f & 31) * 4;
            float4 val = make_float4(0.f, 0.f, 0.f, 0.f);
            if (n0 + r < NN) val = *(const float4*)&h[(n0 + r) * 128 + c4];
            int ci = c4 >> 1;
            hh[r * SPH + hslot(ci)] = pack_h2(val.x, val.y);
            hh[r * SPH + hslot(ci + 1)] = pack_h2(val.z, val.w);
        }
        __syncthreads();
#pragma unroll
        for (int half = 0; half < 2; half++) {
            float acc[4][4];
#pragma unroll
            for (int nt = 0; nt < 4; nt++)
#pragma unroll
                for (int l = 0; l < 4; l++) acc[nt][l] = 0.f;
            gemm_kloop16h(hh, half ? wtB : wtA, mrow, ncol, lane, acc);
            unsigned* out = half ? g_Bh : g_Ah;
#pragma unroll
            for (int nt = 0; nt < 4; nt++) {
                int r = mrow + g;
                int cb = ncol + nt * 8 + tg * 2;
                if (n0 + r < NN)
                    out[(n0 + r) * 64 + (cb >> 1)] = pack_h2(acc[nt][0], acc[nt][1]);
                if (n0 + r + 8 < NN)
                    out[(n0 + r + 8) * 64 + (cb >> 1)] = pack_h2(acc[nt][2], acc[nt][3]);
            }
        }
        __syncthreads();
    }
}

// ---------------- fused edge kernel (persistent, 512 thr, 256-edge tiles) ---
// Row-group g = warp&3 owns tile rows [32g,32g+32) and [128+32g,128+32g+32):
// GEMM A-operands and sgate rows are group-local, so barriers A/B0/B1/C are
// named per-group (bar.sync grp+1, 128). D and E stay block-wide: they order
// the sEA snapshot before next-tile staging (cross-group).
__global__ __launch_bounds__(512, 1) void k_edge(
    const float* __restrict__ x, const float* __restrict__ ea,
    const float* __restrict__ We1, const float* __restrict__ be1,
    const float* __restrict__ We2, const float* __restrict__ be2,
    const float* __restrict__ Wx1, const float* __restrict__ bx1,
    const float* __restrict__ Wx2, const float* __restrict__ bx2,
    float* __restrict__ outx) {
    extern __shared__ float sm[];
    unsigned* tileh = (unsigned*)sm;        // 256*SPH half2 (s -> mm)
    unsigned* wt2h = tileh + 256 * SPH;     // We2^T fp16 perm
    unsigned* wtxh = wt2h + 128 * SPH;      // Wx1^T fp16 perm
    float* sEA = (float*)(wtxh + 128 * SPH);  // 256*EAW
    float* wtE = sEA + 256 * EAW;           // 128*16: edge-attr block, tf32 perm
    float* wds = wtE + 128 * 16;
    float* be1s = wds + 128;
    float* be2s = be1s + 128;
    float* bx1s = be2s + 128;
    float* wx2s = bx1s + 128;
    float* sgate = wx2s + 128;              // 2*256 (double-buffered)

    int tid = threadIdx.x, lane = tid & 31, warp = tid >> 5;
    int grp = warp & 3;

#define BARG() asm volatile("bar.sync %0, %1;" :: "r"(grp + 1), "r"(128) : "memory")

    // ---- one-time staging ----
    stage_wth512(wt2h, We2, tid);
    stage_wth512(wtxh, Wx1, tid);
#pragma unroll
    for (int s = 0; s < 4; s++) {
        int i = s * 512 + tid;
        int n = i & 127, k = i >> 7;
        wtE[n * 16 + kpos(k)] = __uint_as_float(f2tf(We1[(256 + k) * 128 + n]));
    }
    if (tid < 128) {
        wds[tid] = We1[272 * 128 + tid];
        be1s[tid] = be1[tid];
        be2s[tid] = be2[tid];
        bx1s[tid] = bx1[tid];
        wx2s[tid] = Wx2[tid];
    }
    float bx2v = bx2[0];

    // warp tile: M=32 per chunk, N=32; chunks at rows +0 and +128
    int mrow = grp * 32, ncol = (warp >> 2) * 32;
    int g = lane >> 2, tg = lane & 3;
    int e_l = tid >> 1, q = tid & 1;   // 2 threads per edge row for staging

    // ---- stage first tile ----
    {
        int e = blockIdx.x * 256 + e_l;
        *(float4*)&sEA[e_l * EAW + q * 8] = *(const float4*)&ea[e * 16 + q * 8];
        *(float4*)&sEA[e_l * EAW + q * 8 + 4] = *(const float4*)&ea[e * 16 + q * 8 + 4];
        if (q == 0) {
            int si = g_src[e], di = g_dst[e];
            float dx = x[di * 3 + 0] - x[si * 3 + 0];
            float dy = x[di * 3 + 1] - x[si * 3 + 1];
            float dz = x[di * 3 + 2] - x[si * 3 + 2];
            float ss2 = dx * dx + dy * dy + dz * dz;
            float rn = __fdividef(1.0f, sqrtf(ss2) + 1e-9f);
            sEA[e_l * EAW + 16] = sqrtf(ss2 + 1e-9f);
            ((int*)sEA)[e_l * EAW + 17] = si;
            ((int*)sEA)[e_l * EAW + 18] = di;
            sEA[e_l * EAW + 20] = dx * rn;
            sEA[e_l * EAW + 21] = dy * rn;
            sEA[e_l * EAW + 22] = dz * rn;
        }
        if (tid < 256) sgate[tid] = bx2v;
    }
    __syncthreads();

    int pb = 0;
    for (int t = blockIdx.x; t < NT2; t += PGRID) {
        float* sg_cur = sgate + pb * 256;
        float* sg_nxt = sgate + (pb ^ 1) * 256;
        int tn = t + PGRID;
        bool hn = tn < NT2;

        // ---- phase1 (both chunks): ea-GEMM + gather + silu -> tileh --------
#pragma unroll
        for (int ch = 0; ch < 2; ch++) {
            int cb = ch * 128;
            float accA[4][4], accB[4][4];
#pragma unroll
            for (int nt = 0; nt < 4; nt++)
#pragma unroll
                for (int l = 0; l < 4; l++) { accA[nt][l] = 0.f; accB[nt][l] = 0.f; }
            const float* a0p = sEA + (cb + mrow + g) * EAW + tg;
            const float* b0p = wtE + (ncol + g) * 16 + 2 * tg;
#pragma unroll
            for (int kk = 0; kk < 2; kk++) {
                int k0 = kk * 8;
                unsigned aA[4], aB[4];
                aA[0] = f2tf(a0p[k0]);
                aA[1] = f2tf(a0p[8 * EAW + k0]);
                aA[2] = f2tf(a0p[k0 + 4]);
                aA[3] = f2tf(a0p[8 * EAW + k0 + 4]);
                aB[0] = f2tf(a0p[16 * EAW + k0]);
                aB[1] = f2tf(a0p[24 * EAW + k0]);
                aB[2] = f2tf(a0p[16 * EAW + k0 + 4]);
                aB[3] = f2tf(a0p[24 * EAW + k0 + 4]);
#pragma unroll
                for (int nt = 0; nt < 4; nt++) {
                    float2 b = *(const float2*)(b0p + nt * 8 * 16 + k0);
                    unsigned bb[2] = {__float_as_uint(b.x), __float_as_uint(b.y)};
                    mma8(accA[nt], aA, bb);
                    mma8(accB[nt], aB, bb);
                }
            }
#pragma unroll
            for (int rr = 0; rr < 4; rr++) {
                int row = cb + mrow + g + rr * 8;
                float* ac = (rr < 2) ? &accA[0][0] : &accB[0][0];
                int jo = (rr & 1) * 2;
                int si = ((const int*)sEA)[row * EAW + 17];
                int di = ((const int*)sEA)[row * EAW + 18];
                float dist = sEA[row * EAW + 16];
#pragma unroll
                for (int nt = 0; nt < 4; nt++) {
                    int c = ncol + nt * 8 + tg * 2;
                    float2 a2 = unpack_h2(g_Ah[si * 64 + (c >> 1)]);
                    float2 b2 = unpack_h2(g_Bh[di * 64 + (c >> 1)]);
                    float v0 = ac[nt * 4 + jo + 0] + dist * wds[c] + be1s[c] + a2.x + b2.x;
                    float v1 = ac[nt * 4 + jo + 1] + dist * wds[c + 1] + be1s[c + 1] +
                               a2.y + b2.y;
                    tileh[row * SPH + hslot(c >> 1)] = pack_h2(siluf(v0), siluf(v1));
                }
            }
        }
        BARG();  // A (group: s rows complete)

        // ---- GEMM1 chunk0 + agg scatter ----
        float accmA[4][4], accmB[4][4];
#pragma unroll
        for (int nt = 0; nt < 4; nt++) {
            int cb2 = ncol + nt * 8 + tg * 2;
            float b0v = be2s[cb2], b1v = be2s[cb2 + 1];
            accmA[nt][0] = b0v; accmA[nt][1] = b1v;
            accmA[nt][2] = b0v; accmA[nt][3] = b1v;
            accmB[nt][0] = b0v; accmB[nt][1] = b1v;
            accmB[nt][2] = b0v; accmB[nt][3] = b1v;
        }
        gemm_kloop32h(tileh, wt2h, mrow, ncol, lane, accmA, accmB);
#pragma unroll
        for (int rr = 0; rr < 4; rr++) {
            int row = mrow + g + rr * 8;
            const float* ac = (rr < 2) ? &accmA[0][0] : &accmB[0][0];
            int jo = (rr & 1) * 2;
            int di = ((const int*)sEA)[row * EAW + 18];
#pragma unroll
            for (int nt = 0; nt < 4; nt++) {
                float v0 = ac[nt * 4 + jo + 0];
                float v1 = ac[nt * 4 + jo + 1];
                float o0 = __shfl_xor_sync(0xffffffffu, v0, 1);
                float o1 = __shfl_xor_sync(0xffffffffu, v1, 1);
                if ((tg & 1) == 0) {
                    int c = ncol + nt * 8 + tg * 2;
                    asm volatile("red.global.add.v4.f32 [%0], {%1,%2,%3,%4};"
                                 :: "l"(&g_agg[di * 128 + c]),
                                    "f"(v0), "f"(v1), "f"(o0), "f"(o1)
                                 : "memory");
                }
            }
        }
        BARG();  // B0 (group done reading chunk0 s)

        // store mm chunk0, then GEMM1 chunk1 (reads chunk1 s, untouched)
#pragma unroll
        for (int rr = 0; rr < 4; rr++) {
            int row = mrow + g + rr * 8;
            const float* ac = (rr < 2) ? &accmA[0][0] : &accmB[0][0];
            int jo = (rr & 1) * 2;
#pragma unroll
            for (int nt = 0; nt < 4; nt++) {
                int c = ncol + nt * 8 + tg * 2;
                tileh[row * SPH + hslot(c >> 1)] =
                    pack_h2(ac[nt * 4 + jo + 0], ac[nt * 4 + jo + 1]);
            }
        }
#pragma unroll
        for (int nt = 0; nt < 4; nt++) {
            int cb2 = ncol + nt * 8 + tg * 2;
            float b0v = be2s[cb2], b1v = be2s[cb2 + 1];
            accmA[nt][0] = b0v; accmA[nt][1] = b1v;
            accmA[nt][2] = b0v; accmA[nt][3] = b1v;
            accmB[nt][0] = b0v; accmB[nt][1] = b1v;
            accmB[nt][2] = b0v; accmB[nt][3] = b1v;
        }
        gemm_kloop32h(tileh, wt2h, 128 + mrow, ncol, lane, accmA, accmB);
#pragma unroll
        for (int rr = 0; rr < 4; rr++) {
            int row = 128 + mrow + g + rr * 8;
            const float* ac = (rr < 2) ? &accmA[0][0] : &accmB[0][0];
            int jo = (rr & 1) * 2;
            int di = ((const int*)sEA)[row * EAW + 18];
#pragma unroll
            for (int nt = 0; nt < 4; nt++) {
                float v0 = ac[nt * 4 + jo + 0];
                float v1 = ac[nt * 4 + jo + 1];
                float o0 = __shfl_xor_sync(0xffffffffu, v0, 1);
                float o1 = __shfl_xor_sync(0xffffffffu, v1, 1);
                if ((tg & 1) == 0) {
                    int c = ncol + nt * 8 + tg * 2;
                    asm volatile("red.global.add.v4.f32 [%0], {%1,%2,%3,%4};"
                                 :: "l"(&g_agg[di * 128 + c]),
                                    "f"(v0), "f"(v1), "f"(o0), "f"(o1)
                                 : "memory");
                }
            }
        }
        BARG();  // B1 (group done reading chunk1 s; mm0 visible to group)

        // store mm chunk1
#pragma unroll
        for (int rr = 0; rr < 4; rr++) {
            int row = 128 + mrow + g + rr * 8;
            const float* ac = (rr < 2) ? &accmA[0][0] : &accmB[0][0];
            int jo = (rr & 1) * 2;
#pragma unroll
            for (int nt = 0; nt < 4; nt++) {
                int c = ncol + nt * 8 + tg * 2;
                tileh[row * SPH + hslot(c >> 1)] =
                    pack_h2(ac[nt * 4 + jo + 0], ac[nt * 4 + jo + 1]);
            }
        }

        // ---- prefetch next tile (regs) ----
        float4 pea0, pea1;
        int psi = 0, pdi = 0;
        float pdx = 0.f, pdy = 0.f, pdz = 0.f;
        if (hn) {
            int e = tn * 256 + e_l;
            pea0 = *(const float4*)&ea[e * 16 + q * 8];
            pea1 = *(const float4*)&ea[e * 16 + q * 8 + 4];
            if (q == 0) {
                psi = g_src[e];
                pdi = g_dst[e];
                pdx = x[pdi * 3 + 0] - x[psi * 3 + 0];
                pdy = x[pdi * 3 + 1] - x[psi * 3 + 1];
                pdz = x[pdi * 3 + 2] - x[psi * 3 + 2];
            }
        }
        int xdi = 0;
        float xux = 0.f, xuy = 0.f, xuz = 0.f;
        if (tid < 256) {
            xdi = ((const int*)sEA)[tid * EAW + 18];
            xux = sEA[tid * EAW + 20];
            xuy = sEA[tid * EAW + 21];
            xuz = sEA[tid * EAW + 22];
        }

        // ---- GEMM2 chunk0 (mm0 visible since B1) ----
        {
            float accA[4][4], accB[4][4];
#pragma unroll
            for (int nt = 0; nt < 4; nt++) {
                int cb2 = ncol + nt * 8 + tg * 2;
                float b0v = bx1s[cb2], b1v = bx1s[cb2 + 1];
                accA[nt][0] = b0v; accA[nt][1] = b1v;
                accA[nt][2] = b0v; accA[nt][3] = b1v;
                accB[nt][0] = b0v; accB[nt][1] = b1v;
                accB[nt][2] = b0v; accB[nt][3] = b1v;
            }
            gemm_kloop32h(tileh, wtxh, mrow, ncol, lane, accA, accB);
            float p[4] = {0.f, 0.f, 0.f, 0.f};
#pragma unroll
            for (int nt = 0; nt < 4; nt++) {
                int cb2 = ncol + nt * 8 + tg * 2;
                float w0 = wx2s[cb2], w1 = wx2s[cb2 + 1];
                p[0] += siluf(accA[nt][0]) * w0 + siluf(accA[nt][1]) * w1;
                p[1] += siluf(accA[nt][2]) * w0 + siluf(accA[nt][3]) * w1;
                p[2] += siluf(accB[nt][0]) * w0 + siluf(accB[nt][1]) * w1;
                p[3] += siluf(accB[nt][2]) * w0 + siluf(accB[nt][3]) * w1;
            }
#pragma unroll
            for (int i = 0; i < 4; i++) {
                p[i] += __shfl_xor_sync(0xffffffffu, p[i], 1);
                p[i] += __shfl_xor_sync(0xffffffffu, p[i], 2);
            }
            if (tg == 0) {
                atomicAdd(&sg_cur[mrow + g], p[0]);
                atomicAdd(&sg_cur[mrow + g + 8], p[1]);
                atomicAdd(&sg_cur[mrow + g + 16], p[2]);
                atomicAdd(&sg_cur[mrow + g + 24], p[3]);
            }
        }
        BARG();  // C (mm1 visible to group for GEMM2 chunk1)

        // ---- GEMM2 chunk1 ----
        {
            float accA[4][4], accB[4][4];
#pragma unroll
            for (int nt = 0; nt < 4; nt++) {
                int cb2 = ncol + nt * 8 + tg * 2;
                float b0v = bx1s[cb2], b1v = bx1s[cb2 + 1];
                accA[nt][0] = b0v; accA[nt][1] = b1v;
                accA[nt][2] = b0v; accA[nt][3] = b1v;
                accB[nt][0] = b0v; accB[nt][1] = b1v;
                accB[nt][2] = b0v; accB[nt][3] = b1v;
            }
            gemm_kloop32h(tileh, wtxh, 128 + mrow, ncol, lane, accA, accB);
            float p[4] = {0.f, 0.f, 0.f, 0.f};
#pragma unroll
            for (int nt = 0; nt < 4; nt++) {
                int cb2 = ncol + nt * 8 + tg * 2;
                float w0 = wx2s[cb2], w1 = wx2s[cb2 + 1];
                p[0] += siluf(accA[nt][0]) * w0 + siluf(accA[nt][1]) * w1;
                p[1] += siluf(accA[nt][2]) * w0 + siluf(accA[nt][3]) * w1;
                p[2] += siluf(accB[nt][0]) * w0 + siluf(accB[nt][1]) * w1;
                p[3] += siluf(accB[nt][2]) * w0 + siluf(accB[nt][3]) * w1;
            }
#pragma unroll
            for (int i = 0; i < 4; i++) {
                p[i] += __shfl_xor_sync(0xffffffffu, p[i], 1);
                p[i] += __shfl_xor_sync(0xffffffffu, p[i], 2);
            }
            if (tg == 0) {
                atomicAdd(&sg_cur[128 + mrow + g], p[0]);
                atomicAdd(&sg_cur[128 + mrow + g + 8], p[1]);
                atomicAdd(&sg_cur[128 + mrow + g + 16], p[2]);
                atomicAdd(&sg_cur[128 + mrow + g + 24], p[3]);
            }
        }
        __syncthreads();  // D (block-wide: sgate complete; snapshots done before staging)

        // ---- x scatter (precomputed dir) + stage next tile ----
        if (tid < 256) {
            float gte = sg_cur[tid];
            atomicAdd(&outx[xdi * 3 + 0], xux * gte);
            atomicAdd(&outx[xdi * 3 + 1], xuy * gte);
            atomicAdd(&outx[xdi * 3 + 2], xuz * gte);
            sg_nxt[tid] = bx2v;
        }
        if (hn) {
            *(float4*)&sEA[e_l * EAW + q * 8] = pea0;
            *(float4*)&sEA[e_l * EAW + q * 8 + 4] = pea1;
            if (q == 0) {
                float ss2 = pdx * pdx + pdy * pdy + pdz * pdz;
                float rn = __fdividef(1.0f, sqrtf(ss2) + 1e-9f);
                sEA[e_l * EAW + 16] = sqrtf(ss2 + 1e-9f);
                ((int*)sEA)[e_l * EAW + 17] = psi;
                ((int*)sEA)[e_l * EAW + 18] = pdi;
                sEA[e_l * EAW + 20] = pdx * rn;
                sEA[e_l * EAW + 21] = pdy * rn;
                sEA[e_l * EAW + 22] = pdz * rn;
            }
        }
        __syncthreads();  // E
        pb ^= 1;
    }
#undef BARG
}

// ---------------- node update (persistent, 1024 thr, fp16 GEMMs) ------------
__global__ __launch_bounds__(1024, 1) void k_node_upd(
    const float* __restrict__ h, const float* __restrict__ Wh1,
    const float* __restrict__ bh1, const float* __restrict__ Wh2,
    const float* __restrict__ bh2, const float* __restrict__ lng,
    const float* __restrict__ lnb, float* __restrict__ outh) {
    extern __shared__ float sm[];
    float* hr = sm;                        // 128*SP fp32 (residual + LN)
    unsigned* hh = (unsigned*)(hr + 128 * SP);  // 128*SPH h half2 perm
    unsigned* ap = hh + 128 * SPH;         // 128*SPH agg -> tt half2 perm
    unsigned* wt = ap + 128 * SPH;         // 128*SPH weight half2 perm
    float* bh1s = (float*)(wt + 128 * SPH);
    float* bh2s = bh1s + 128;
    float* lngs = bh2s + 128;
    float* lnbs = lngs + 128;
    float* ssum = lnbs + 128;
    float* ssq = ssum + 128;

    int tid = threadIdx.x, lane = tid & 31, warp = tid >> 5;
    if (tid < 128) {
        bh1s[tid] = bh1[tid];
        bh2s[tid] = bh2[tid];
        lngs[tid] = lng[tid];
        lnbs[tid] = lnb[tid];
    }

    int mrow = (warp >> 2) * 16, ncol = (warp & 3) * 32;
    int g = lane >> 2, tg = lane & 3;

    for (int t = blockIdx.x; t < NTILE_N; t += gridDim.x) {
        int n0 = t * 128;
        if (tid < 128) {
            ssum[tid] = 0.f;
            ssq[tid] = 0.f;
        }
#pragma unroll
        for (int v = 0; v < 4; v++) {
            int f = v * 1024 + tid;
            int r = f >> 5, c4 = (f & 31) * 4;
            float4 hv = make_float4(0.f, 0.f, 0.f, 0.f);
            float4 av = make_float4(0.f, 0.f, 0.f, 0.f);
            if (n0 + r < NN) {
                hv = *(const float4*)&h[(n0 + r) * 128 + c4];
                av = *(const float4*)&g_agg[(n0 + r) * 128 + c4];
            }
            *(float4*)&hr[r * SP + c4] = hv;
            int ci = c4 >> 1;
            hh[r * SPH + hslot(ci)] = pack_h2(hv.x, hv.y);
            hh[r * SPH + hslot(ci + 1)] = pack_h2(hv.z, hv.w);
            ap[r * SPH + hslot(ci)] = pack_h2(av.x, av.y);
            ap[r * SPH + hslot(ci + 1)] = pack_h2(av.z, av.w);
        }
        stage_wth1024(wt, Wh1, tid);
        __syncthreads();

        float acc[4][4];
#pragma unroll
        for (int nt = 0; nt < 4; nt++) {
            int cb = ncol + nt * 8 + tg * 2;
            float b0v = bh1s[cb], b1v = bh1s[cb + 1];
            acc[nt][0] = b0v; acc[nt][1] = b1v;
            acc[nt][2] = b0v; acc[nt][3] = b1v;
        }
        gemm_kloop16h(hh, wt, mrow, ncol, lane, acc);
        __syncthreads();
        stage_wth1024(wt, Wh1 + 128 * 128, tid);
        __syncthreads();
        gemm_kloop16h(ap, wt, mrow, ncol, lane, acc);
        __syncthreads();

#pragma unroll
        for (int rr = 0; rr < 2; rr++) {
            int row = mrow + g + rr * 8;
#pragma unroll
            for (int nt = 0; nt < 4; nt++) {
                int c = ncol + nt * 8 + tg * 2;
                ap[row * SPH + hslot(c >> 1)] =
                    pack_h2(siluf(acc[nt][rr * 2 + 0]), siluf(acc[nt][rr * 2 + 1]));
            }
        }
        stage_wth1024(wt, Wh2, tid);
        __syncthreads();

        float acc2[4][4];
#pragma unroll
        for (int nt = 0; nt < 4; nt++) {
            int cb = ncol + nt * 8 + tg * 2;
            float b0v = bh2s[cb], b1v = bh2s[cb + 1];
            acc2[nt][0] = b0v; acc2[nt][1] = b1v;
            acc2[nt][2] = b0v; acc2[nt][3] = b1v;
        }
        gemm_kloop16h(ap, wt, mrow, ncol, lane, acc2);

        float vsum[2] = {0.f, 0.f}, vsq[2] = {0.f, 0.f};
#pragma unroll
        for (int rr = 0; rr < 2; rr++) {
            int row = mrow + g + rr * 8;
#pragma unroll
            for (int nt = 0; nt < 4; nt++) {
                int cb = ncol + nt * 8 + tg * 2;
                float v0 = hr[row * SP + cb] + acc2[nt][rr * 2 + 0];
                float v1 = hr[row * SP + cb + 1] + acc2[nt][rr * 2 + 1];
                acc2[nt][rr * 2 + 0] = v0;
                acc2[nt][rr * 2 + 1] = v1;
                vsum[rr] += v0 + v1;
                vsq[rr] += v0 * v0 + v1 * v1;
            }
        }
#pragma unroll
        for (int i = 0; i < 2; i++) {
            vsum[i] += __shfl_xor_sync(0xffffffffu, vsum[i], 1);
            vsum[i] += __shfl_xor_sync(0xffffffffu, vsum[i], 2);
            vsq[i] += __shfl_xor_sync(0xffffffffu, vsq[i], 1);
            vsq[i] += __shfl_xor_sync(0xffffffffu, vsq[i], 2);
        }
        if (tg == 0) {
            atomicAdd(&ssum[mrow + g], vsum[0]);
            atomicAdd(&ssq[mrow + g], vsq[0]);
            atomicAdd(&ssum[mrow + g + 8], vsum[1]);
            atomicAdd(&ssq[mrow + g + 8], vsq[1]);
        }
        __syncthreads();

#pragma unroll
        for (int rr = 0; rr < 2; rr++) {
            int row = mrow + g + rr * 8;
            float mean = ssum[row] * (1.0f / 128.0f);
            float var = ssq[row] * (1.0f / 128.0f) - mean * mean;
            float rstd = rsqrtf(var + 1e-5f);
            if (n0 + row < NN) {
#pragma unroll
                for (int nt = 0; nt < 4; nt++) {
                    int cb = ncol + nt * 8 + tg * 2;
                    *(float2*)&outh[(n0 + row) * 128 + cb] = make_float2(
                        (acc2[nt][rr * 2 + 0] - mean) * rstd * lngs[cb] + lnbs[cb],
                        (acc2[nt][rr * 2 + 1] - mean) * rstd * lngs[cb + 1] + lnbs[cb + 1]);
                }
            }
        }
        __syncthreads();
    }
}

// ---------------- launcher ---------------------------------------------------
extern "C" void kernel_launch(void* const* d_in, const int* in_sizes, int n_in,
                              void* d_out, int out_size) {
    const float* h = (const float*)d_in[0];
    const float* x = (const float*)d_in[1];
    const void* ei = d_in[2];
    const float* ea = (const float*)d_in[3];
    const float* We1 = (const float*)d_in[4];
    const float* be1 = (const float*)d_in[5];
    const float* We2 = (const float*)d_in[6];
    const float* be2 = (const float*)d_in[7];
    const float* Wh1 = (const float*)d_in[8];
    const float* bh1 = (const float*)d_in[9];
    const float* Wh2 = (const float*)d_in[10];
    const float* bh2 = (const float*)d_in[11];
    const float* Wx1 = (const float*)d_in[12];
    const float* bx1 = (const float*)d_in[13];
    const float* Wx2 = (const float*)d_in[14];
    const float* bx2 = (const float*)d_in[15];
    const float* lng = (const float*)d_in[16];
    const float* lnb = (const float*)d_in[17];

    float* outh = (float*)d_out;
    float* outx = outh + (size_t)NN * 128;

    const int SMEM_EDGE =
        (256 * SPH + 2 * 128 * SPH + 256 * EAW + 128 * 16 + 5 * 128 + 512) * 4;  // 184832
    const int SMEM_PRE = (3 * 128 * SPH) * 4;                                     // 110592
    const int SMEM_UPD = (128 * SP + 3 * 128 * SPH + 6 * 128) * 4;                // 183296
    cudaFuncSetAttribute(k_edge, cudaFuncAttributeMaxDynamicSharedMemorySize, SMEM_EDGE);
    cudaFuncSetAttribute(k_node_pre, cudaFuncAttributeMaxDynamicSharedMemorySize, SMEM_PRE);
    cudaFuncSetAttribute(k_node_upd, cudaFuncAttributeMaxDynamicSharedMemorySize, SMEM_UPD);

    k_detect<<<1, 32>>>(ei);
    k_prep<<<1024, 256>>>(ei, x, outx);
    k_node_pre<<<PGRID, 1024, SMEM_PRE>>>(h, We1);
    k_edge<<<PGRID, 512, SMEM_EDGE>>>(x, ea, We1, be1, We2, be2, Wx1, bx1, Wx2,
                                      bx2, outx);
    k_node_upd<<<PGRID, 1024, SMEM_UPD>>>(h, Wh1, bh1, Wh2, bh2, lng, lnb, outh);
}